// round 6
// baseline (speedup 1.0000x reference)
#include <cuda_runtime.h>

typedef unsigned long long ull;

// ---------------- dimensions ----------------
static constexpr int DA = 45, DB = 102;

// ---------------- shared layout (floats); all weight rows / tile offsets 16B-aligned ----
static constexpr int OFF_Wa = 0;        // 45 x 68
static constexpr int OFF_ba = 3060;     // 68
static constexpr int OFF_Wb = 3128;     // 102 x 68
static constexpr int OFF_bb = 10064;    // 68
static constexpr int OFF_W0 = 10132;    // 140 x 36 (padded from 34)
static constexpr int OFF_B0 = 15172;    // 36
static constexpr int OFF_W1 = 15208;    // 34 x 36 (padded)
static constexpr int OFF_B1 = 16432;    // 36
static constexpr int OFF_W2 = 16468;    // 34 x 20
static constexpr int OFF_B2 = 17148;    // 20
static constexpr int OFF_W3 = 17168;    static constexpr int OFF_B3 = 17568;
static constexpr int OFF_W4 = 17588;    static constexpr int OFF_B4 = 17988;
static constexpr int OFF_W5 = 18008;    static constexpr int OFF_B5 = 18408;
static constexpr int OFF_W6 = 18428;    static constexpr int OFF_B6 = 18828;
static constexpr int OFF_W7 = 18848;    // 20 x 8 (padded from 20x5)
static constexpr int OFF_B7 = 19008;    // 8
static constexpr int OFF_W8 = 19016;    // 5 x 4 (padded from 5x2)
static constexpr int OFF_B8 = 19036;    // 4
static constexpr int OFF_W9 = 19040;    // [w9_0, w9_1, b9, 0]
static constexpr int OFF_STAGE = 19044; // 12 warps x 64 rows x stride 34 (duplicated x pairs)
static constexpr int STG_STRIDE = 34;   // even (STS.64-aligned), conflict-free
static constexpr int STG_WARP = 64 * STG_STRIDE;                   // 2176
static constexpr int SMEM_FLOATS = OFF_STAGE + 12 * STG_WARP;      // 45156
static constexpr int SMEM_BYTES = SMEM_FLOATS * 4;                 // 180624

static constexpr int NGROUPS = 262144 / 64;  // 4096 warp-groups of 64 rows

__device__ int g_ctr;

__global__ void reset_ctr_kernel() { g_ctr = 0; }

// ---------------- f32x2 helpers ----------------
__device__ __forceinline__ ull pack2(float x, float y) {
    ull r; asm("mov.b64 %0, {%1, %2};" : "=l"(r) : "f"(x), "f"(y)); return r;
}
__device__ __forceinline__ void unpack2(ull v, float& x, float& y) {
    asm("mov.b64 {%0, %1}, %2;" : "=f"(x), "=f"(y) : "l"(v));
}
__device__ __forceinline__ ull ffma2(ull a, ull b, ull c) {
    ull d; asm("fma.rn.f32x2 %0, %1, %2, %3;" : "=l"(d) : "l"(a), "l"(b), "l"(c)); return d;
}
__device__ __forceinline__ float lrelu(float x) { return fmaxf(x, 0.01f * x); }

// acc layout per ulonglong2 p (output cols 4p..4p+3):
//   acc[4p+0]=rowA(4p,4p+1) acc[4p+1]=rowB(4p,4p+1) acc[4p+2]=rowA(4p+2,4p+3) acc[4p+3]=rowB(4p+2,4p+3)
template <int NW2>
__device__ __forceinline__ void init_pair(ull* acc, const float* __restrict__ bsrc) {
#pragma unroll
    for (int p = 0; p < NW2; p++) {
        ulonglong2 w = *reinterpret_cast<const ulonglong2*>(bsrc + 4 * p);
        acc[4 * p + 0] = w.x; acc[4 * p + 1] = w.x;
        acc[4 * p + 2] = w.y; acc[4 * p + 3] = w.y;
    }
}

template <int NW2>
__device__ __forceinline__ void rank1_pair(ull* acc, const ulonglong2* __restrict__ wr,
                                           ull xs0, ull xs1) {
#pragma unroll
    for (int p = 0; p < NW2; p++) {
        ulonglong2 w = wr[p];
        acc[4 * p + 0] = ffma2(xs0, w.x, acc[4 * p + 0]);
        acc[4 * p + 1] = ffma2(xs1, w.x, acc[4 * p + 1]);
        acc[4 * p + 2] = ffma2(xs0, w.y, acc[4 * p + 2]);
        acc[4 * p + 3] = ffma2(xs1, w.y, acc[4 * p + 3]);
    }
}

// Stage chunk [k0,k0+cv) of 64 rows as duplicated (x,x) pairs. Coalesced LDG, conflict-free STS.64.
template <int K>
__device__ __forceinline__ void stage_chunk(const float* __restrict__ gw, int k0, int cv,
                                            float* __restrict__ stg, int lane) {
    __syncwarp();
    const int c = lane & 15, rh = lane >> 4;
    if (c < cv) {
        const float* g = gw + (size_t)rh * K + k0 + c;
        float* s = stg + rh * STG_STRIDE + 2 * c;
#pragma unroll 8
        for (int r = 0; r < 32; r++) {
            float x = *g;
            *reinterpret_cast<float2*>(s) = make_float2(x, x);
            g += 2 * K;
            s += 2 * STG_STRIDE;
        }
    }
    __syncwarp();
}

// One tower column-tile: K-wide GEMV into 4*NW2 accs (2 rows x 2*NW2 col-pairs).
// smw points at the tile's first weight column; row stride 68 floats.
template <int K, int NW2>
__device__ __forceinline__ void tower_tile(const float* __restrict__ gw,
                                           const float* __restrict__ smw,
                                           float* __restrict__ stg, int lane, ull* acc) {
    for (int k0 = 0; k0 < K; k0 += 16) {
        int cv = K - k0; if (cv > 16) cv = 16;
        stage_chunk<K>(gw, k0, cv, stg, lane);
        const float* xA = stg + lane * STG_STRIDE;
        const float* xB = stg + (lane + 32) * STG_STRIDE;
#pragma unroll 4
        for (int k = 0; k < cv; k++) {
            ull xs0 = *reinterpret_cast<const ull*>(xA + 2 * k);
            ull xs1 = *reinterpret_cast<const ull*>(xB + 2 * k);
            rank1_pair<NW2>(acc, reinterpret_cast<const ulonglong2*>(smw + (size_t)(k0 + k) * 68),
                            xs0, xs1);
        }
    }
}

// Feed one concat index (both rows) into the 36-wide layer-0 accumulator (acc0: 36 ull).
__device__ __forceinline__ void feed0_pair(float va, float vb, int kidx,
                                           const float* __restrict__ sm, ull* acc0) {
    ull xs0 = pack2(va, va), xs1 = pack2(vb, vb);
    rank1_pair<9>(acc0, reinterpret_cast<const ulonglong2*>(sm + OFF_W0 + kidx * 36), xs0, xs1);
}

// LeakyReLU a tower tile's outputs and feed into acc0 at concat offset cbase.
template <int NW2>
__device__ __forceinline__ void feed_tower(const ull* acc, int cbase,
                                           const float* __restrict__ sm, ull* acc0) {
#pragma unroll
    for (int p = 0; p < NW2; p++) {
        float a0, a1, b0, b1;
        unpack2(acc[4 * p + 0], a0, a1);
        unpack2(acc[4 * p + 1], b0, b1);
        feed0_pair(lrelu(a0), lrelu(b0), cbase + 4 * p + 0, sm, acc0);
        feed0_pair(lrelu(a1), lrelu(b1), cbase + 4 * p + 1, sm, acc0);
        unpack2(acc[4 * p + 2], a0, a1);
        unpack2(acc[4 * p + 3], b0, b1);
        feed0_pair(lrelu(a0), lrelu(b0), cbase + 4 * p + 2, sm, acc0);
        feed0_pair(lrelu(a1), lrelu(b1), cbase + 4 * p + 3, sm, acc0);
    }
}

// Dense column-tile for both rows: writes 4*NW2 activated outputs at outA/outB.
// WS = full weight row stride (floats); woff points at tile's first column.
template <int K, int NW2, int WS, int INN>
__device__ __forceinline__ void dense_tile(const float (&inA)[INN], const float (&inB)[INN],
                                           float* __restrict__ outA, float* __restrict__ outB,
                                           const float* __restrict__ sm, int woff, int boff) {
    static_assert(INN >= K, "bad dims");
    ull acc[4 * NW2];
    init_pair<NW2>(acc, sm + boff);
#pragma unroll
    for (int k = 0; k < K; k++) {
        ull xs0 = pack2(inA[k], inA[k]), xs1 = pack2(inB[k], inB[k]);
        rank1_pair<NW2>(acc, reinterpret_cast<const ulonglong2*>(sm + woff + k * WS), xs0, xs1);
    }
#pragma unroll
    for (int p = 0; p < NW2; p++) {
        float v0, v1;
        unpack2(acc[4 * p + 0], v0, v1); outA[4 * p + 0] = lrelu(v0); outA[4 * p + 1] = lrelu(v1);
        unpack2(acc[4 * p + 1], v0, v1); outB[4 * p + 0] = lrelu(v0); outB[4 * p + 1] = lrelu(v1);
        unpack2(acc[4 * p + 2], v0, v1); outA[4 * p + 2] = lrelu(v0); outA[4 * p + 3] = lrelu(v1);
        unpack2(acc[4 * p + 3], v0, v1); outB[4 * p + 2] = lrelu(v0); outB[4 * p + 3] = lrelu(v1);
    }
}

__global__ __launch_bounds__(384, 1)
void Net_67954972557347_kernel(
    const float* __restrict__ a, const float* __restrict__ b, const float* __restrict__ meta,
    const float* __restrict__ Wa, const float* __restrict__ ba,
    const float* __restrict__ Wb, const float* __restrict__ bb,
    const float* __restrict__ W0, const float* __restrict__ B0,
    const float* __restrict__ W1, const float* __restrict__ B1,
    const float* __restrict__ W2, const float* __restrict__ B2,
    const float* __restrict__ W3, const float* __restrict__ B3,
    const float* __restrict__ W4, const float* __restrict__ B4,
    const float* __restrict__ W5, const float* __restrict__ B5,
    const float* __restrict__ W6, const float* __restrict__ B6,
    const float* __restrict__ W7, const float* __restrict__ B7,
    const float* __restrict__ W8, const float* __restrict__ B8,
    const float* __restrict__ W9, const float* __restrict__ B9,
    float* __restrict__ outp, int nrows)
{
    extern __shared__ float sm[];
    const int tid = threadIdx.x, nt = blockDim.x;
    const int lane = tid & 31, warp = tid >> 5;

    // ---- stage weights (one-time) ----
    for (int i = tid; i < 45 * 68; i += nt) sm[OFF_Wa + i] = Wa[i];
    for (int i = tid; i < 68; i += nt) sm[OFF_ba + i] = ba[i];
    for (int i = tid; i < 102 * 68; i += nt) sm[OFF_Wb + i] = Wb[i];
    for (int i = tid; i < 68; i += nt) sm[OFF_bb + i] = bb[i];
    for (int i = tid; i < 140 * 36; i += nt) { int r = i / 36, c = i - r * 36; sm[OFF_W0 + i] = (c < 34) ? W0[r * 34 + c] : 0.0f; }
    for (int i = tid; i < 36; i += nt) sm[OFF_B0 + i] = (i < 34) ? B0[i] : 0.0f;
    for (int i = tid; i < 34 * 36; i += nt) { int r = i / 36, c = i - r * 36; sm[OFF_W1 + i] = (c < 34) ? W1[r * 34 + c] : 0.0f; }
    for (int i = tid; i < 36; i += nt) sm[OFF_B1 + i] = (i < 34) ? B1[i] : 0.0f;
    for (int i = tid; i < 34 * 20; i += nt) sm[OFF_W2 + i] = W2[i];
    for (int i = tid; i < 20; i += nt) sm[OFF_B2 + i] = B2[i];
    for (int i = tid; i < 400; i += nt) sm[OFF_W3 + i] = W3[i];
    for (int i = tid; i < 20; i += nt) sm[OFF_B3 + i] = B3[i];
    for (int i = tid; i < 400; i += nt) sm[OFF_W4 + i] = W4[i];
    for (int i = tid; i < 20; i += nt) sm[OFF_B4 + i] = B4[i];
    for (int i = tid; i < 400; i += nt) sm[OFF_W5 + i] = W5[i];
    for (int i = tid; i < 20; i += nt) sm[OFF_B5 + i] = B5[i];
    for (int i = tid; i < 400; i += nt) sm[OFF_W6 + i] = W6[i];
    for (int i = tid; i < 20; i += nt) sm[OFF_B6 + i] = B6[i];
    for (int i = tid; i < 20 * 8; i += nt) { int r = i >> 3, c = i & 7; sm[OFF_W7 + i] = (c < 5) ? W7[r * 5 + c] : 0.0f; }
    for (int i = tid; i < 8; i += nt) sm[OFF_B7 + i] = (i < 5) ? B7[i] : 0.0f;
    for (int i = tid; i < 5 * 4; i += nt) { int r = i >> 2, c = i & 3; sm[OFF_W8 + i] = (c < 2) ? W8[r * 2 + c] : 0.0f; }
    for (int i = tid; i < 4; i += nt) sm[OFF_B8 + i] = (i < 2) ? B8[i] : 0.0f;
    if (tid == 0) { sm[OFF_W9 + 0] = W9[0]; sm[OFF_W9 + 1] = W9[1]; sm[OFF_W9 + 2] = B9[0]; sm[OFF_W9 + 3] = 0.0f; }
    __syncthreads();

    float* stg = sm + OFF_STAGE + warp * STG_WARP;

    for (;;) {
        // warp-level work stealing: grab a 64-row group
        int g;
        if (lane == 0) g = atomicAdd(&g_ctr, 1);
        g = __shfl_sync(0xFFFFFFFFu, g, 0);
        if (g >= NGROUPS) break;

        const int wbase = g << 6;
        const int r0 = wbase + lane, r1 = r0 + 32;
        const float* ga = a + (size_t)wbase * DA;
        const float* gb = b + (size_t)wbase * DB;

        ull acc0[36];
        init_pair<9>(acc0, sm + OFF_B0);

        // tower a -> concat[0..67], 4 column tiles (20/16/16/16)
        { ull t[20]; init_pair<5>(t, sm + OFF_ba +  0); tower_tile<DA, 5>(ga, sm + OFF_Wa +  0, stg, lane, t); feed_tower<5>(t,  0, sm, acc0); }
        { ull t[16]; init_pair<4>(t, sm + OFF_ba + 20); tower_tile<DA, 4>(ga, sm + OFF_Wa + 20, stg, lane, t); feed_tower<4>(t, 20, sm, acc0); }
        { ull t[16]; init_pair<4>(t, sm + OFF_ba + 36); tower_tile<DA, 4>(ga, sm + OFF_Wa + 36, stg, lane, t); feed_tower<4>(t, 36, sm, acc0); }
        { ull t[16]; init_pair<4>(t, sm + OFF_ba + 52); tower_tile<DA, 4>(ga, sm + OFF_Wa + 52, stg, lane, t); feed_tower<4>(t, 52, sm, acc0); }
        // tower b -> concat[68..135]
        { ull t[20]; init_pair<5>(t, sm + OFF_bb +  0); tower_tile<DB, 5>(gb, sm + OFF_Wb +  0, stg, lane, t); feed_tower<5>(t,  68, sm, acc0); }
        { ull t[16]; init_pair<4>(t, sm + OFF_bb + 20); tower_tile<DB, 4>(gb, sm + OFF_Wb + 20, stg, lane, t); feed_tower<4>(t,  88, sm, acc0); }
        { ull t[16]; init_pair<4>(t, sm + OFF_bb + 36); tower_tile<DB, 4>(gb, sm + OFF_Wb + 36, stg, lane, t); feed_tower<4>(t, 104, sm, acc0); }
        { ull t[16]; init_pair<4>(t, sm + OFF_bb + 52); tower_tile<DB, 4>(gb, sm + OFF_Wb + 52, stg, lane, t); feed_tower<4>(t, 120, sm, acc0); }
        // meta -> concat[136..139] (no activation on meta)
        {
            float4 mA = *reinterpret_cast<const float4*>(meta + (size_t)r0 * 4);
            float4 mB = *reinterpret_cast<const float4*>(meta + (size_t)r1 * 4);
            feed0_pair(mA.x, mB.x, 136, sm, acc0);
            feed0_pair(mA.y, mB.y, 137, sm, acc0);
            feed0_pair(mA.z, mB.z, 138, sm, acc0);
            feed0_pair(mA.w, mB.w, 139, sm, acc0);
        }

        float c1A[36], c1B[36];
#pragma unroll
        for (int p = 0; p < 9; p++) {
            float v0, v1;
            unpack2(acc0[4 * p + 0], v0, v1); c1A[4 * p + 0] = lrelu(v0); c1A[4 * p + 1] = lrelu(v1);
            unpack2(acc0[4 * p + 1], v0, v1); c1B[4 * p + 0] = lrelu(v0); c1B[4 * p + 1] = lrelu(v1);
            unpack2(acc0[4 * p + 2], v0, v1); c1A[4 * p + 2] = lrelu(v0); c1A[4 * p + 3] = lrelu(v1);
            unpack2(acc0[4 * p + 3], v0, v1); c1B[4 * p + 2] = lrelu(v0); c1B[4 * p + 3] = lrelu(v1);
        }

        // layer 1 (34->34, padded 36), 3 tiles of 12 cols to bound live regs
        float c2A[36], c2B[36];
        dense_tile<34, 3, 36>(c1A, c1B, c2A +  0, c2B +  0, sm, OFF_W1 +  0, OFF_B1 +  0);
        dense_tile<34, 3, 36>(c1A, c1B, c2A + 12, c2B + 12, sm, OFF_W1 + 12, OFF_B1 + 12);
        dense_tile<34, 3, 36>(c1A, c1B, c2A + 24, c2B + 24, sm, OFF_W1 + 24, OFF_B1 + 24);

        float c3A[20], c3B[20]; dense_tile<34, 5, 20>(c2A, c2B, c3A, c3B, sm, OFF_W2, OFF_B2);
        float c4A[20], c4B[20]; dense_tile<20, 5, 20>(c3A, c3B, c4A, c4B, sm, OFF_W3, OFF_B3);
        float c5A[20], c5B[20]; dense_tile<20, 5, 20>(c4A, c4B, c5A, c5B, sm, OFF_W4, OFF_B4);
        float c6A[20], c6B[20]; dense_tile<20, 5, 20>(c5A, c5B, c6A, c6B, sm, OFF_W5, OFF_B5);
        float c7A[20], c7B[20]; dense_tile<20, 5, 20>(c6A, c6B, c7A, c7B, sm, OFF_W6, OFF_B6);
        float c8A[8],  c8B[8];  dense_tile<20, 2,  8>(c7A, c7B, c8A, c8B, sm, OFF_W7, OFF_B7);
        float c9A[4],  c9B[4];  dense_tile<5, 1,  4>(c8A, c8B, c9A, c9B, sm, OFF_W8, OFF_B8);

        float oA = fmaf(c9A[0], sm[OFF_W9 + 0], fmaf(c9A[1], sm[OFF_W9 + 1], sm[OFF_W9 + 2]));
        float oB = fmaf(c9B[0], sm[OFF_W9 + 0], fmaf(c9B[1], sm[OFF_W9 + 1], sm[OFF_W9 + 2]));
        outp[r0] = lrelu(oA);
        outp[r1] = lrelu(oB);
    }
}

extern "C" void kernel_launch(void* const* d_in, const int* in_sizes, int n_in,
                              void* d_out, int out_size) {
    const float* a    = (const float*)d_in[0];
    const float* b    = (const float*)d_in[1];
    const float* meta = (const float*)d_in[2];
    const float* Wa   = (const float*)d_in[3];
    const float* ba   = (const float*)d_in[4];
    const float* Wb   = (const float*)d_in[5];
    const float* bb   = (const float*)d_in[6];
    const float* W[10], *Bb[10];
    for (int i = 0; i < 10; i++) {
        W[i]  = (const float*)d_in[7 + 2 * i];
        Bb[i] = (const float*)d_in[8 + 2 * i];
    }
    float* outp = (float*)d_out;
    const int nrows = in_sizes[0] / DA;

    cudaFuncSetAttribute(Net_67954972557347_kernel,
                         cudaFuncAttributeMaxDynamicSharedMemorySize, SMEM_BYTES);

    reset_ctr_kernel<<<1, 1>>>();
    // 180.6KB smem -> 1 block/SM; 384 threads = 12 warps (3/SMSP); warp-level work stealing.
    Net_67954972557347_kernel<<<148, 384, SMEM_BYTES>>>(
        a, b, meta, Wa, ba, Wb, bb,
        W[0], Bb[0], W[1], Bb[1], W[2], Bb[2], W[3], Bb[3], W[4], Bb[4],
        W[5], Bb[5], W[6], Bb[6], W[7], Bb[7], W[8], Bb[8], W[9], Bb[9],
        outp, nrows);
}

// round 7
// speedup vs baseline: 1.0004x; 1.0004x over previous
#include <cuda_runtime.h>

typedef unsigned long long ull;

// ---------------- dimensions ----------------
static constexpr int DA = 45, DB = 102;

// ---------------- shared layout (floats); all weight rows / tile offsets 16B-aligned ----
static constexpr int OFF_Wa = 0;        // 45 x 68
static constexpr int OFF_ba = 3060;     // 68
static constexpr int OFF_Wb = 3128;     // 102 x 68
static constexpr int OFF_bb = 10064;    // 68
static constexpr int OFF_W0 = 10132;    // 140 x 36 (padded from 34)
static constexpr int OFF_B0 = 15172;    // 36
static constexpr int OFF_W1 = 15208;    // 34 x 36 (padded)
static constexpr int OFF_B1 = 16432;    // 36
static constexpr int OFF_W2 = 16468;    // 34 x 20
static constexpr int OFF_B2 = 17148;    // 20
static constexpr int OFF_W3 = 17168;    static constexpr int OFF_B3 = 17568;
static constexpr int OFF_W4 = 17588;    static constexpr int OFF_B4 = 17988;
static constexpr int OFF_W5 = 18008;    static constexpr int OFF_B5 = 18408;
static constexpr int OFF_W6 = 18428;    static constexpr int OFF_B6 = 18828;
static constexpr int OFF_W7 = 18848;    // 20 x 8 (padded from 20x5)
static constexpr int OFF_B7 = 19008;    // 8
static constexpr int OFF_W8 = 19016;    // 5 x 4 (padded from 5x2)
static constexpr int OFF_B8 = 19036;    // 4
static constexpr int OFF_W9 = 19040;    // [w9_0, w9_1, b9, 0]
static constexpr int OFF_STAGE = 19044; // 12 warps x 64 rows x stride 34 (duplicated x pairs)
static constexpr int STG_STRIDE = 34;   // even (STS.64-aligned), conflict-free
static constexpr int STG_WARP = 64 * STG_STRIDE;                   // 2176
static constexpr int SMEM_FLOATS = OFF_STAGE + 12 * STG_WARP;      // 45156
static constexpr int SMEM_BYTES = SMEM_FLOATS * 4;                 // 180624

static constexpr int NGROUPS = 262144 / 64;  // 4096 warp-groups of 64 rows

__device__ int g_ctr;

__global__ void reset_ctr_kernel() { g_ctr = 0; }

// ---------------- f32x2 helpers ----------------
__device__ __forceinline__ ull pack2(float x, float y) {
    ull r; asm("mov.b64 %0, {%1, %2};" : "=l"(r) : "f"(x), "f"(y)); return r;
}
__device__ __forceinline__ void unpack2(ull v, float& x, float& y) {
    asm("mov.b64 {%0, %1}, %2;" : "=f"(x), "=f"(y) : "l"(v));
}
__device__ __forceinline__ ull ffma2(ull a, ull b, ull c) {
    ull d; asm("fma.rn.f32x2 %0, %1, %2, %3;" : "=l"(d) : "l"(a), "l"(b), "l"(c)); return d;
}
__device__ __forceinline__ float lrelu(float x) { return fmaxf(x, 0.01f * x); }

// acc layout per ulonglong2 p (output cols 4p..4p+3):
//   acc[4p+0]=rowA(4p,4p+1) acc[4p+1]=rowB(4p,4p+1) acc[4p+2]=rowA(4p+2,4p+3) acc[4p+3]=rowB(4p+2,4p+3)
template <int NW2>
__device__ __forceinline__ void init_pair(ull* acc, const float* __restrict__ bsrc) {
#pragma unroll
    for (int p = 0; p < NW2; p++) {
        ulonglong2 w = *reinterpret_cast<const ulonglong2*>(bsrc + 4 * p);
        acc[4 * p + 0] = w.x; acc[4 * p + 1] = w.x;
        acc[4 * p + 2] = w.y; acc[4 * p + 3] = w.y;
    }
}

template <int NW2>
__device__ __forceinline__ void rank1_pair(ull* acc, const ulonglong2* __restrict__ wr,
                                           ull xs0, ull xs1) {
#pragma unroll
    for (int p = 0; p < NW2; p++) {
        ulonglong2 w = wr[p];
        acc[4 * p + 0] = ffma2(xs0, w.x, acc[4 * p + 0]);
        acc[4 * p + 1] = ffma2(xs1, w.x, acc[4 * p + 1]);
        acc[4 * p + 2] = ffma2(xs0, w.y, acc[4 * p + 2]);
        acc[4 * p + 3] = ffma2(xs1, w.y, acc[4 * p + 3]);
    }
}

// Stage chunk [k0,k0+cv) of 64 rows as duplicated (x,x) pairs. Coalesced LDG, conflict-free STS.64.
template <int K>
__device__ __forceinline__ void stage_chunk(const float* __restrict__ gw, int k0, int cv,
                                            float* __restrict__ stg, int lane) {
    __syncwarp();
    const int c = lane & 15, rh = lane >> 4;
    if (c < cv) {
        const float* g = gw + (size_t)rh * K + k0 + c;
        float* s = stg + rh * STG_STRIDE + 2 * c;
#pragma unroll 8
        for (int r = 0; r < 32; r++) {
            float x = *g;
            *reinterpret_cast<float2*>(s) = make_float2(x, x);
            g += 2 * K;
            s += 2 * STG_STRIDE;
        }
    }
    __syncwarp();
}

// One tower column-tile: K-wide GEMV into 4*NW2 accs (2 rows x 2*NW2 col-pairs).
// smw points at the tile's first weight column; row stride 68 floats.
template <int K, int NW2>
__device__ __forceinline__ void tower_tile(const float* __restrict__ gw,
                                           const float* __restrict__ smw,
                                           float* __restrict__ stg, int lane, ull* acc) {
    for (int k0 = 0; k0 < K; k0 += 16) {
        int cv = K - k0; if (cv > 16) cv = 16;
        stage_chunk<K>(gw, k0, cv, stg, lane);
        const float* xA = stg + lane * STG_STRIDE;
        const float* xB = stg + (lane + 32) * STG_STRIDE;
#pragma unroll 4
        for (int k = 0; k < cv; k++) {
            ull xs0 = *reinterpret_cast<const ull*>(xA + 2 * k);
            ull xs1 = *reinterpret_cast<const ull*>(xB + 2 * k);
            rank1_pair<NW2>(acc, reinterpret_cast<const ulonglong2*>(smw + (size_t)(k0 + k) * 68),
                            xs0, xs1);
        }
    }
}

// Feed one concat index (both rows) into the 36-wide layer-0 accumulator (acc0: 36 ull).
__device__ __forceinline__ void feed0_pair(float va, float vb, int kidx,
                                           const float* __restrict__ sm, ull* acc0) {
    ull xs0 = pack2(va, va), xs1 = pack2(vb, vb);
    rank1_pair<9>(acc0, reinterpret_cast<const ulonglong2*>(sm + OFF_W0 + kidx * 36), xs0, xs1);
}

// LeakyReLU a tower tile's outputs and feed into acc0 at concat offset cbase.
template <int NW2>
__device__ __forceinline__ void feed_tower(const ull* acc, int cbase,
                                           const float* __restrict__ sm, ull* acc0) {
#pragma unroll
    for (int p = 0; p < NW2; p++) {
        float a0, a1, b0, b1;
        unpack2(acc[4 * p + 0], a0, a1);
        unpack2(acc[4 * p + 1], b0, b1);
        feed0_pair(lrelu(a0), lrelu(b0), cbase + 4 * p + 0, sm, acc0);
        feed0_pair(lrelu(a1), lrelu(b1), cbase + 4 * p + 1, sm, acc0);
        unpack2(acc[4 * p + 2], a0, a1);
        unpack2(acc[4 * p + 3], b0, b1);
        feed0_pair(lrelu(a0), lrelu(b0), cbase + 4 * p + 2, sm, acc0);
        feed0_pair(lrelu(a1), lrelu(b1), cbase + 4 * p + 3, sm, acc0);
    }
}

// Dense column-tile for both rows: writes 4*NW2 activated outputs at outA/outB.
// WS = full weight row stride (floats); woff points at tile's first column.
template <int K, int NW2, int WS, int INN>
__device__ __forceinline__ void dense_tile(const float (&inA)[INN], const float (&inB)[INN],
                                           float* __restrict__ outA, float* __restrict__ outB,
                                           const float* __restrict__ sm, int woff, int boff) {
    static_assert(INN >= K, "bad dims");
    ull acc[4 * NW2];
    init_pair<NW2>(acc, sm + boff);
#pragma unroll
    for (int k = 0; k < K; k++) {
        ull xs0 = pack2(inA[k], inA[k]), xs1 = pack2(inB[k], inB[k]);
        rank1_pair<NW2>(acc, reinterpret_cast<const ulonglong2*>(sm + woff + k * WS), xs0, xs1);
    }
#pragma unroll
    for (int p = 0; p < NW2; p++) {
        float v0, v1;
        unpack2(acc[4 * p + 0], v0, v1); outA[4 * p + 0] = lrelu(v0); outA[4 * p + 1] = lrelu(v1);
        unpack2(acc[4 * p + 1], v0, v1); outB[4 * p + 0] = lrelu(v0); outB[4 * p + 1] = lrelu(v1);
        unpack2(acc[4 * p + 2], v0, v1); outA[4 * p + 2] = lrelu(v0); outA[4 * p + 3] = lrelu(v1);
        unpack2(acc[4 * p + 3], v0, v1); outB[4 * p + 2] = lrelu(v0); outB[4 * p + 3] = lrelu(v1);
    }
}

__global__ __launch_bounds__(384, 1)
void Net_67954972557347_kernel(
    const float* __restrict__ a, const float* __restrict__ b, const float* __restrict__ meta,
    const float* __restrict__ Wa, const float* __restrict__ ba,
    const float* __restrict__ Wb, const float* __restrict__ bb,
    const float* __restrict__ W0, const float* __restrict__ B0,
    const float* __restrict__ W1, const float* __restrict__ B1,
    const float* __restrict__ W2, const float* __restrict__ B2,
    const float* __restrict__ W3, const float* __restrict__ B3,
    const float* __restrict__ W4, const float* __restrict__ B4,
    const float* __restrict__ W5, const float* __restrict__ B5,
    const float* __restrict__ W6, const float* __restrict__ B6,
    const float* __restrict__ W7, const float* __restrict__ B7,
    const float* __restrict__ W8, const float* __restrict__ B8,
    const float* __restrict__ W9, const float* __restrict__ B9,
    float* __restrict__ outp, int nrows)
{
    extern __shared__ float sm[];
    const int tid = threadIdx.x, nt = blockDim.x;
    const int lane = tid & 31, warp = tid >> 5;

    // ---- stage weights (one-time) ----
    for (int i = tid; i < 45 * 68; i += nt) sm[OFF_Wa + i] = Wa[i];
    for (int i = tid; i < 68; i += nt) sm[OFF_ba + i] = ba[i];
    for (int i = tid; i < 102 * 68; i += nt) sm[OFF_Wb + i] = Wb[i];
    for (int i = tid; i < 68; i += nt) sm[OFF_bb + i] = bb[i];
    for (int i = tid; i < 140 * 36; i += nt) { int r = i / 36, c = i - r * 36; sm[OFF_W0 + i] = (c < 34) ? W0[r * 34 + c] : 0.0f; }
    for (int i = tid; i < 36; i += nt) sm[OFF_B0 + i] = (i < 34) ? B0[i] : 0.0f;
    for (int i = tid; i < 34 * 36; i += nt) { int r = i / 36, c = i - r * 36; sm[OFF_W1 + i] = (c < 34) ? W1[r * 34 + c] : 0.0f; }
    for (int i = tid; i < 36; i += nt) sm[OFF_B1 + i] = (i < 34) ? B1[i] : 0.0f;
    for (int i = tid; i < 34 * 20; i += nt) sm[OFF_W2 + i] = W2[i];
    for (int i = tid; i < 20; i += nt) sm[OFF_B2 + i] = B2[i];
    for (int i = tid; i < 400; i += nt) sm[OFF_W3 + i] = W3[i];
    for (int i = tid; i < 20; i += nt) sm[OFF_B3 + i] = B3[i];
    for (int i = tid; i < 400; i += nt) sm[OFF_W4 + i] = W4[i];
    for (int i = tid; i < 20; i += nt) sm[OFF_B4 + i] = B4[i];
    for (int i = tid; i < 400; i += nt) sm[OFF_W5 + i] = W5[i];
    for (int i = tid; i < 20; i += nt) sm[OFF_B5 + i] = B5[i];
    for (int i = tid; i < 400; i += nt) sm[OFF_W6 + i] = W6[i];
    for (int i = tid; i < 20; i += nt) sm[OFF_B6 + i] = B6[i];
    for (int i = tid; i < 20 * 8; i += nt) { int r = i >> 3, c = i & 7; sm[OFF_W7 + i] = (c < 5) ? W7[r * 5 + c] : 0.0f; }
    for (int i = tid; i < 8; i += nt) sm[OFF_B7 + i] = (i < 5) ? B7[i] : 0.0f;
    for (int i = tid; i < 5 * 4; i += nt) { int r = i >> 2, c = i & 3; sm[OFF_W8 + i] = (c < 2) ? W8[r * 2 + c] : 0.0f; }
    for (int i = tid; i < 4; i += nt) sm[OFF_B8 + i] = (i < 2) ? B8[i] : 0.0f;
    if (tid == 0) { sm[OFF_W9 + 0] = W9[0]; sm[OFF_W9 + 1] = W9[1]; sm[OFF_W9 + 2] = B9[0]; sm[OFF_W9 + 3] = 0.0f; }
    __syncthreads();

    float* stg = sm + OFF_STAGE + warp * STG_WARP;

    for (;;) {
        // warp-level work stealing: grab a 64-row group
        int g;
        if (lane == 0) g = atomicAdd(&g_ctr, 1);
        g = __shfl_sync(0xFFFFFFFFu, g, 0);
        if (g >= NGROUPS) break;

        const int wbase = g << 6;
        const int r0 = wbase + lane, r1 = r0 + 32;
        const float* ga = a + (size_t)wbase * DA;
        const float* gb = b + (size_t)wbase * DB;

        ull acc0[36];
        init_pair<9>(acc0, sm + OFF_B0);

        // tower a -> concat[0..67], 4 column tiles (20/16/16/16)
        { ull t[20]; init_pair<5>(t, sm + OFF_ba +  0); tower_tile<DA, 5>(ga, sm + OFF_Wa +  0, stg, lane, t); feed_tower<5>(t,  0, sm, acc0); }
        { ull t[16]; init_pair<4>(t, sm + OFF_ba + 20); tower_tile<DA, 4>(ga, sm + OFF_Wa + 20, stg, lane, t); feed_tower<4>(t, 20, sm, acc0); }
        { ull t[16]; init_pair<4>(t, sm + OFF_ba + 36); tower_tile<DA, 4>(ga, sm + OFF_Wa + 36, stg, lane, t); feed_tower<4>(t, 36, sm, acc0); }
        { ull t[16]; init_pair<4>(t, sm + OFF_ba + 52); tower_tile<DA, 4>(ga, sm + OFF_Wa + 52, stg, lane, t); feed_tower<4>(t, 52, sm, acc0); }
        // tower b -> concat[68..135]
        { ull t[20]; init_pair<5>(t, sm + OFF_bb +  0); tower_tile<DB, 5>(gb, sm + OFF_Wb +  0, stg, lane, t); feed_tower<5>(t,  68, sm, acc0); }
        { ull t[16]; init_pair<4>(t, sm + OFF_bb + 20); tower_tile<DB, 4>(gb, sm + OFF_Wb + 20, stg, lane, t); feed_tower<4>(t,  88, sm, acc0); }
        { ull t[16]; init_pair<4>(t, sm + OFF_bb + 36); tower_tile<DB, 4>(gb, sm + OFF_Wb + 36, stg, lane, t); feed_tower<4>(t, 104, sm, acc0); }
        { ull t[16]; init_pair<4>(t, sm + OFF_bb + 52); tower_tile<DB, 4>(gb, sm + OFF_Wb + 52, stg, lane, t); feed_tower<4>(t, 120, sm, acc0); }
        // meta -> concat[136..139] (no activation on meta)
        {
            float4 mA = *reinterpret_cast<const float4*>(meta + (size_t)r0 * 4);
            float4 mB = *reinterpret_cast<const float4*>(meta + (size_t)r1 * 4);
            feed0_pair(mA.x, mB.x, 136, sm, acc0);
            feed0_pair(mA.y, mB.y, 137, sm, acc0);
            feed0_pair(mA.z, mB.z, 138, sm, acc0);
            feed0_pair(mA.w, mB.w, 139, sm, acc0);
        }

        float c1A[36], c1B[36];
#pragma unroll
        for (int p = 0; p < 9; p++) {
            float v0, v1;
            unpack2(acc0[4 * p + 0], v0, v1); c1A[4 * p + 0] = lrelu(v0); c1A[4 * p + 1] = lrelu(v1);
            unpack2(acc0[4 * p + 1], v0, v1); c1B[4 * p + 0] = lrelu(v0); c1B[4 * p + 1] = lrelu(v1);
            unpack2(acc0[4 * p + 2], v0, v1); c1A[4 * p + 2] = lrelu(v0); c1A[4 * p + 3] = lrelu(v1);
            unpack2(acc0[4 * p + 3], v0, v1); c1B[4 * p + 2] = lrelu(v0); c1B[4 * p + 3] = lrelu(v1);
        }

        // layer 1 (34->34, padded 36), 3 tiles of 12 cols to bound live regs
        float c2A[36], c2B[36];
        dense_tile<34, 3, 36>(c1A, c1B, c2A +  0, c2B +  0, sm, OFF_W1 +  0, OFF_B1 +  0);
        dense_tile<34, 3, 36>(c1A, c1B, c2A + 12, c2B + 12, sm, OFF_W1 + 12, OFF_B1 + 12);
        dense_tile<34, 3, 36>(c1A, c1B, c2A + 24, c2B + 24, sm, OFF_W1 + 24, OFF_B1 + 24);

        float c3A[20], c3B[20]; dense_tile<34, 5, 20>(c2A, c2B, c3A, c3B, sm, OFF_W2, OFF_B2);
        float c4A[20], c4B[20]; dense_tile<20, 5, 20>(c3A, c3B, c4A, c4B, sm, OFF_W3, OFF_B3);
        float c5A[20], c5B[20]; dense_tile<20, 5, 20>(c4A, c4B, c5A, c5B, sm, OFF_W4, OFF_B4);
        float c6A[20], c6B[20]; dense_tile<20, 5, 20>(c5A, c5B, c6A, c6B, sm, OFF_W5, OFF_B5);
        float c7A[20], c7B[20]; dense_tile<20, 5, 20>(c6A, c6B, c7A, c7B, sm, OFF_W6, OFF_B6);
        float c8A[8],  c8B[8];  dense_tile<20, 2,  8>(c7A, c7B, c8A, c8B, sm, OFF_W7, OFF_B7);
        float c9A[4],  c9B[4];  dense_tile<5, 1,  4>(c8A, c8B, c9A, c9B, sm, OFF_W8, OFF_B8);

        float oA = fmaf(c9A[0], sm[OFF_W9 + 0], fmaf(c9A[1], sm[OFF_W9 + 1], sm[OFF_W9 + 2]));
        float oB = fmaf(c9B[0], sm[OFF_W9 + 0], fmaf(c9B[1], sm[OFF_W9 + 1], sm[OFF_W9 + 2]));
        outp[r0] = lrelu(oA);
        outp[r1] = lrelu(oB);
    }
}

extern "C" void kernel_launch(void* const* d_in, const int* in_sizes, int n_in,
                              void* d_out, int out_size) {
    const float* a    = (const float*)d_in[0];
    const float* b    = (const float*)d_in[1];
    const float* meta = (const float*)d_in[2];
    const float* Wa   = (const float*)d_in[3];
    const float* ba   = (const float*)d_in[4];
    const float* Wb   = (const float*)d_in[5];
    const float* bb   = (const float*)d_in[6];
    const float* W[10], *Bb[10];
    for (int i = 0; i < 10; i++) {
        W[i]  = (const float*)d_in[7 + 2 * i];
        Bb[i] = (const float*)d_in[8 + 2 * i];
    }
    float* outp = (float*)d_out;
    const int nrows = in_sizes[0] / DA;

    cudaFuncSetAttribute(Net_67954972557347_kernel,
                         cudaFuncAttributeMaxDynamicSharedMemorySize, SMEM_BYTES);

    reset_ctr_kernel<<<1, 1>>>();
    // 180.6KB smem -> 1 block/SM; 384 threads = 12 warps (3/SMSP); warp-level work stealing.
    Net_67954972557347_kernel<<<148, 384, SMEM_BYTES>>>(
        a, b, meta, Wa, ba, Wb, bb,
        W[0], Bb[0], W[1], Bb[1], W[2], Bb[2], W[3], Bb[3], W[4], Bb[4],
        W[5], Bb[5], W[6], Bb[6], W[7], Bb[7], W[8], Bb[8], W[9], Bb[9],
        outp, nrows);
}

// round 11
// speedup vs baseline: 2.9163x; 2.9153x over previous
#include <cuda_runtime.h>
#include <cuda_bf16.h>
#include <cstdint>

typedef unsigned long long ull;
typedef uint32_t u32;

// ---------------- fragment arena byte offsets (256 B per 16x8 B-fragment) ----------------
static constexpr u32 TA_H = 0;      // towerA: Kp=48,Np=72 -> 3*9=27 frags
static constexpr u32 TA_L = 6912;
static constexpr u32 TB_H = 13824;  // towerB: Kp=112,Np=72 -> 7*9=63
static constexpr u32 TB_L = 29952;
static constexpr u32 L0_H = 46080;  // L0: Kp=160,Np=40 -> 10*5=50
static constexpr u32 L0_L = 58880;
static constexpr u32 L1_H = 71680;  // L1: Kp=48,Np=40 -> 15
static constexpr u32 L1_L = 75520;
static constexpr u32 L2_H = 79360;  // L2: Kp=48,Np=24 -> 9
static constexpr u32 L2_L = 81664;
static constexpr u32 L3_H = 83968;  // L3-6: Kp=32,Np=24 -> 6
static constexpr u32 L3_L = 85504;
static constexpr u32 L4_H = 87040;
static constexpr u32 L4_L = 88576;
static constexpr u32 L5_H = 90112;
static constexpr u32 L5_L = 91648;
static constexpr u32 L6_H = 93184;
static constexpr u32 L6_L = 94720;
static constexpr u32 L7_H = 96256;  // L7: Kp=32,Np=8 -> 2
static constexpr u32 L7_L = 96768;
static constexpr u32 BIAS_B = 97280;       // float arena
static constexpr u32 SMEM_TOTAL = 98816;   // 96.5 KB -> 2 CTAs/SM

// bias-arena float indices (all even -> float2-aligned)
static constexpr int JTA = 0, JTB = 72, J0 = 144, J1 = 184, J2 = 224, J3 = 248;
static constexpr int J4 = 272, J5 = 296, J6 = 320, J7 = 344;
static constexpr int JW8 = 352, JB8 = 368, JW9 = 370, JB9 = 372;  // W8 padded 8x2

__device__ __forceinline__ float lrelu(float x) { return fmaxf(x, 0.01f * x); }

// pack two f32 into bf16x2 (v0 -> low half)
__device__ __forceinline__ u32 cvtpack(float v0, float v1) {
    u32 r; asm("cvt.rn.bf16x2.f32 %0, %1, %2;" : "=r"(r) : "f"(v1), "f"(v0)); return r;
}
// hi/lo split pack: h = bf16(v), l = bf16(v - f32(h))
__device__ __forceinline__ void split_pack(float v0, float v1, u32& h, u32& l) {
    h = cvtpack(v0, v1);
    float h0 = __uint_as_float(h << 16);
    float h1 = __uint_as_float(h & 0xFFFF0000u);
    l = cvtpack(v0 - h0, v1 - h1);
}

__device__ __forceinline__ void mma16816(float& c0, float& c1, float& c2, float& c3,
                                         u32 a0, u32 a1, u32 a2, u32 a3, u32 b0, u32 b1) {
    asm volatile(
        "mma.sync.aligned.m16n8k16.row.col.f32.bf16.bf16.f32 "
        "{%0,%1,%2,%3}, {%4,%5,%6,%7}, {%8,%9}, {%0,%1,%2,%3};"
        : "+f"(c0), "+f"(c1), "+f"(c2), "+f"(c3)
        : "r"(a0), "r"(a1), "r"(a2), "r"(a3), "r"(b0), "r"(b1));
}

// D(nblk) -> A slot s: h[2s] from rows g (d0,d1), h[2s+1] from rows g+8 (d2,d3)
__device__ __forceinline__ void toslot(float d0, float d1, float d2, float d3,
                                       u32* h, u32* l, int s, bool act) {
    if (act) { d0 = lrelu(d0); d1 = lrelu(d1); d2 = lrelu(d2); d3 = lrelu(d3); }
    split_pack(d0, d1, h[2 * s + 0], l[2 * s + 0]);
    split_pack(d2, d3, h[2 * s + 1], l[2 * s + 1]);
}

// bounds-checked split load of 2 consecutive activations
__device__ __forceinline__ void ld_split(const float* __restrict__ p, int c, int Kreal,
                                         u32& h, u32& l) {
    float v0 = (c < Kreal) ? __ldg(p + c) : 0.0f;
    float v1 = (c + 1 < Kreal) ? __ldg(p + c + 1) : 0.0f;
    split_pack(v0, v1, h, l);
}

// One layer: D = bias + Ah*Wh + Al*Wh + Ah*Wl. KB k-blocks, NB n8-blocks.
template <int KB, int NB>
__device__ __forceinline__ void layer(const u32* Ah, const u32* Al, const char* smc,
                                      u32 offH, u32 offL, int bidx, int lane, float* D) {
    const int t2 = (lane & 3) << 1;
    const float* biasp = reinterpret_cast<const float*>(smc + BIAS_B) + bidx;
#pragma unroll
    for (int nb = 0; nb < NB; nb++) {
        float2 bv = *reinterpret_cast<const float2*>(biasp + nb * 8 + t2);
        float c0 = bv.x, c1 = bv.y, c2 = bv.x, c3 = bv.y;
        const char* ph = smc + offH + nb * 256 + (lane << 3);
        const char* pl = smc + offL + nb * 256 + (lane << 3);
#pragma unroll
        for (int kb = 0; kb < KB; kb++) {
            ull w = *reinterpret_cast<const ull*>(ph + kb * (NB * 256));
            u32 b0 = (u32)w, b1 = (u32)(w >> 32);
            mma16816(c0, c1, c2, c3, Ah[4 * kb], Ah[4 * kb + 1], Ah[4 * kb + 2], Ah[4 * kb + 3], b0, b1);
            mma16816(c0, c1, c2, c3, Al[4 * kb], Al[4 * kb + 1], Al[4 * kb + 2], Al[4 * kb + 3], b0, b1);
        }
#pragma unroll
        for (int kb = 0; kb < KB; kb++) {
            ull w = *reinterpret_cast<const ull*>(pl + kb * (NB * 256));
            mma16816(c0, c1, c2, c3, Ah[4 * kb], Ah[4 * kb + 1], Ah[4 * kb + 2], Ah[4 * kb + 3],
                     (u32)w, (u32)(w >> 32));
        }
        D[4 * nb + 0] = c0; D[4 * nb + 1] = c1; D[4 * nb + 2] = c2; D[4 * nb + 3] = c3;
    }
}

// W [K,N] row-major fp32 -> hi/lo B fragments. mode 1 = L0 concat row remap.
__device__ void prepW(char* smc, const float* __restrict__ W, int K, int N, int NBfr,
                      u32 offH, u32 offL, int tid, int mode) {
    for (int i = tid; i < K * N; i += 128) {
        int k = i / N, n = i - k * N;
        int kp = k;
        if (mode == 1) kp = (k < 68) ? k : ((k < 136) ? k + 4 : k + 8);
        // B frag layout: col n = lane>>2; k: b0 holds 2*(lane&3)+{0,1}, b1 = +8
        u32 fo = (u32)(((kp >> 4) * NBfr + (n >> 3)) << 8)
               + (u32)((((n & 7) << 2) | ((kp & 7) >> 1)) << 3)
               + (u32)(((kp >> 3) & 1) << 2)
               + (u32)((kp & 1) << 1);
        float v = W[i];
        __nv_bfloat16 h = __float2bfloat16(v);
        float lo = v - __bfloat162float(h);
        *reinterpret_cast<__nv_bfloat16*>(smc + offH + fo) = h;
        *reinterpret_cast<__nv_bfloat16*>(smc + offL + fo) = __float2bfloat16(lo);
    }
}

__global__ __launch_bounds__(128)
void Net_67954972557347_kernel(
    const float* __restrict__ a, const float* __restrict__ b, const float* __restrict__ meta,
    const float* __restrict__ Wa, const float* __restrict__ ba,
    const float* __restrict__ Wb, const float* __restrict__ bb,
    const float* __restrict__ W0, const float* __restrict__ B0,
    const float* __restrict__ W1, const float* __restrict__ B1,
    const float* __restrict__ W2, const float* __restrict__ B2,
    const float* __restrict__ W3, const float* __restrict__ B3,
    const float* __restrict__ W4, const float* __restrict__ B4,
    const float* __restrict__ W5, const float* __restrict__ B5,
    const float* __restrict__ W6, const float* __restrict__ B6,
    const float* __restrict__ W7, const float* __restrict__ B7,
    const float* __restrict__ W8, const float* __restrict__ B8,
    const float* __restrict__ W9, const float* __restrict__ B9,
    float* __restrict__ outp, int ntiles)
{
    extern __shared__ char smc[];
    const int tid = threadIdx.x, lane = tid & 31, warp = tid >> 5;

    // zero arenas (pads stay zero)
    for (u32 o = (u32)tid * 16; o < SMEM_TOTAL; o += 128 * 16)
        *reinterpret_cast<uint4*>(smc + o) = make_uint4(0, 0, 0, 0);
    __syncthreads();

    prepW(smc, Wa, 45, 68, 9, TA_H, TA_L, tid, 0);
    prepW(smc, Wb, 102, 68, 9, TB_H, TB_L, tid, 0);
    prepW(smc, W0, 140, 34, 5, L0_H, L0_L, tid, 1);
    prepW(smc, W1, 34, 34, 5, L1_H, L1_L, tid, 0);
    prepW(smc, W2, 34, 20, 3, L2_H, L2_L, tid, 0);
    prepW(smc, W3, 20, 20, 3, L3_H, L3_L, tid, 0);
    prepW(smc, W4, 20, 20, 3, L4_H, L4_L, tid, 0);
    prepW(smc, W5, 20, 20, 3, L5_H, L5_L, tid, 0);
    prepW(smc, W6, 20, 20, 3, L6_H, L6_L, tid, 0);
    prepW(smc, W7, 20, 5, 1, L7_H, L7_L, tid, 0);
    float* bs = reinterpret_cast<float*>(smc + BIAS_B);
    if (tid < 68) { bs[JTA + tid] = ba[tid]; bs[JTB + tid] = bb[tid]; }
    if (tid < 34) { bs[J0 + tid] = B0[tid]; bs[J1 + tid] = B1[tid]; }
    if (tid < 20) {
        bs[J2 + tid] = B2[tid]; bs[J3 + tid] = B3[tid]; bs[J4 + tid] = B4[tid];
        bs[J5 + tid] = B5[tid]; bs[J6 + tid] = B6[tid];
    }
    if (tid < 5)  bs[J7 + tid] = B7[tid];
    if (tid < 10) bs[JW8 + tid] = W8[tid];       // [k*2+n], rows 5-7 stay 0
    if (tid < 2)  { bs[JB8 + tid] = B8[tid]; bs[JW9 + tid] = W9[tid]; }
    if (tid == 0) bs[JB9] = B9[0];
    __syncthreads();

    const int t2 = (lane & 3) << 1;

    for (int tile = blockIdx.x * 4 + warp; tile < ntiles; tile += gridDim.x * 4) {
        const int r0 = tile * 16 + (lane >> 2), r1 = r0 + 8;
        u32 h0[40], l0[40];   // layer-0 A fragments (20 slots x 2)

        {   // tower A: K=45(pad48), N=72 -> slots 0..8
            u32 fh[12], fl[12];
            const float* p0 = a + (size_t)r0 * 45;
            const float* p1 = a + (size_t)r1 * 45;
#pragma unroll
            for (int kb = 0; kb < 3; kb++) {
                int c = kb * 16 + t2;
                ld_split(p0, c, 45, fh[4 * kb + 0], fl[4 * kb + 0]);
                ld_split(p1, c, 45, fh[4 * kb + 1], fl[4 * kb + 1]);
                ld_split(p0, c + 8, 45, fh[4 * kb + 2], fl[4 * kb + 2]);
                ld_split(p1, c + 8, 45, fh[4 * kb + 3], fl[4 * kb + 3]);
            }
            float D[36];
            layer<3, 9>(fh, fl, smc, TA_H, TA_L, JTA, lane, D);
#pragma unroll
            for (int nb = 0; nb < 9; nb++)
                toslot(D[4 * nb], D[4 * nb + 1], D[4 * nb + 2], D[4 * nb + 3], h0, l0, nb, true);
        }
        {   // tower B: K=102(pad112), N=72 -> slots 9..17
            u32 fh[28], fl[28];
            const float* p0 = b + (size_t)r0 * 102;
            const float* p1 = b + (size_t)r1 * 102;
#pragma unroll
            for (int kb = 0; kb < 7; kb++) {
                int c = kb * 16 + t2;
                ld_split(p0, c, 102, fh[4 * kb + 0], fl[4 * kb + 0]);
                ld_split(p1, c, 102, fh[4 * kb + 1], fl[4 * kb + 1]);
                ld_split(p0, c + 8, 102, fh[4 * kb + 2], fl[4 * kb + 2]);
                ld_split(p1, c + 8, 102, fh[4 * kb + 3], fl[4 * kb + 3]);
            }
            float D[36];
            layer<7, 9>(fh, fl, smc, TB_H, TB_L, JTB, lane, D);
#pragma unroll
            for (int nb = 0; nb < 9; nb++)
                toslot(D[4 * nb], D[4 * nb + 1], D[4 * nb + 2], D[4 * nb + 3], h0, l0, 9 + nb, true);
        }
        {   // meta -> slot 18 (cols 144-151; no lrelu), slot 19 zero
            float m0x = 0, m0y = 0, m1x = 0, m1y = 0;
            if (t2 < 4) {
                float2 u = *reinterpret_cast<const float2*>(meta + (size_t)r0 * 4 + t2);
                float2 v = *reinterpret_cast<const float2*>(meta + (size_t)r1 * 4 + t2);
                m0x = u.x; m0y = u.y; m1x = v.x; m1y = v.y;
            }
            toslot(m0x, m0y, m1x, m1y, h0, l0, 18, false);
            h0[38] = 0; h0[39] = 0; l0[38] = 0; l0[39] = 0;
        }

        u32 h1[12], l1[12];
        {   // L0: K=160, N=40
            float D[20];
            layer<10, 5>(h0, l0, smc, L0_H, L0_L, J0, lane, D);
#pragma unroll
            for (int nb = 0; nb < 5; nb++)
                toslot(D[4 * nb], D[4 * nb + 1], D[4 * nb + 2], D[4 * nb + 3], h1, l1, nb, true);
            h1[10] = 0; h1[11] = 0; l1[10] = 0; l1[11] = 0;
        }
        {   // L1: K=48, N=40
            float D[20];
            layer<3, 5>(h1, l1, smc, L1_H, L1_L, J1, lane, D);
#pragma unroll
            for (int nb = 0; nb < 5; nb++)
                toslot(D[4 * nb], D[4 * nb + 1], D[4 * nb + 2], D[4 * nb + 3], h1, l1, nb, true);
            h1[10] = 0; h1[11] = 0; l1[10] = 0; l1[11] = 0;
        }
        {   // L2: K=48, N=24
            float D[12];
            layer<3, 3>(h1, l1, smc, L2_H, L2_L, J2, lane, D);
#pragma unroll
            for (int nb = 0; nb < 3; nb++)
                toslot(D[4 * nb], D[4 * nb + 1], D[4 * nb + 2], D[4 * nb + 3], h1, l1, nb, true);
            h1[6] = 0; h1[7] = 0; l1[6] = 0; l1[7] = 0;
        }
        // L3..L6: K=32, N=24
        const u32 lh[4] = { L3_H, L4_H, L5_H, L6_H };
        const u32 ll[4] = { L3_L, L4_L, L5_L, L6_L };
        const int lj[4] = { J3, J4, J5, J6 };
#pragma unroll
        for (int L = 0; L < 4; L++) {
            float D[12];
            layer<2, 3>(h1, l1, smc, lh[L], ll[L], lj[L], lane, D);
#pragma unroll
            for (int nb = 0; nb < 3; nb++)
                toslot(D[4 * nb], D[4 * nb + 1], D[4 * nb + 2], D[4 * nb + 3], h1, l1, nb, true);
            h1[6] = 0; h1[7] = 0; l1[6] = 0; l1[7] = 0;
        }
        // L7: K=32, N=8
        float D7[4];
        layer<2, 1>(h1, l1, smc, L7_H, L7_L, J7, lane, D7);
        float v0 = lrelu(D7[0]), v1 = lrelu(D7[1]), v2 = lrelu(D7[2]), v3 = lrelu(D7[3]);

        // L8 (5->2) + L9 (2->1) scalar; 4-lane butterfly per row group
        float w8a0 = bs[JW8 + t2 * 2 + 0], w8b0 = bs[JW8 + t2 * 2 + 1];
        float w8a1 = bs[JW8 + (t2 + 1) * 2 + 0], w8b1 = bs[JW8 + (t2 + 1) * 2 + 1];
        float pa0 = fmaf(v0, w8a0, v1 * w8a1), pb0 = fmaf(v0, w8b0, v1 * w8b1);
        float pa1 = fmaf(v2, w8a0, v3 * w8a1), pb1 = fmaf(v2, w8b0, v3 * w8b1);
        pa0 += __shfl_xor_sync(0xFFFFFFFFu, pa0, 1); pa0 += __shfl_xor_sync(0xFFFFFFFFu, pa0, 2);
        pb0 += __shfl_xor_sync(0xFFFFFFFFu, pb0, 1); pb0 += __shfl_xor_sync(0xFFFFFFFFu, pb0, 2);
        pa1 += __shfl_xor_sync(0xFFFFFFFFu, pa1, 1); pa1 += __shfl_xor_sync(0xFFFFFFFFu, pa1, 2);
        pb1 += __shfl_xor_sync(0xFFFFFFFFu, pb1, 1); pb1 += __shfl_xor_sync(0xFFFFFFFFu, pb1, 2);
        float w90 = bs[JW9 + 0], w91 = bs[JW9 + 1], b9v = bs[JB9];
        float c8a = lrelu(pa0 + bs[JB8 + 0]), c8b = lrelu(pb0 + bs[JB8 + 1]);
        float o0 = lrelu(fmaf(c8a, w90, fmaf(c8b, w91, b9v)));
        c8a = lrelu(pa1 + bs[JB8 + 0]); c8b = lrelu(pb1 + bs[JB8 + 1]);
        float o1 = lrelu(fmaf(c8a, w90, fmaf(c8b, w91, b9v)));
        if ((lane & 3) == 0) { outp[r0] = o0; outp[r1] = o1; }
    }
}

extern "C" void kernel_launch(void* const* d_in, const int* in_sizes, int n_in,
                              void* d_out, int out_size) {
    const float* a    = (const float*)d_in[0];
    const float* b    = (const float*)d_in[1];
    const float* meta = (const float*)d_in[2];
    const float* Wa   = (const float*)d_in[3];
    const float* ba   = (const float*)d_in[4];
    const float* Wb   = (const float*)d_in[5];
    const float* bb   = (const float*)d_in[6];
    const float* W[10], *Bb[10];
    for (int i = 0; i < 10; i++) {
        W[i]  = (const float*)d_in[7 + 2 * i];
        Bb[i] = (const float*)d_in[8 + 2 * i];
    }
    float* outp = (float*)d_out;
    const int nrows = in_sizes[0] / 45;
    const int ntiles = nrows / 16;   // 16384

    cudaFuncSetAttribute(Net_67954972557347_kernel,
                         cudaFuncAttributeMaxDynamicSharedMemorySize, SMEM_TOTAL);

    // 96.5 KB smem -> 2 CTAs/SM; 128 threads = 4 independent warps per CTA.
    Net_67954972557347_kernel<<<296, 128, SMEM_TOTAL>>>(
        a, b, meta, Wa, ba, Wb, bb,
        W[0], Bb[0], W[1], Bb[1], W[2], Bb[2], W[3], Bb[3], W[4], Bb[4],
        W[5], Bb[5], W[6], Bb[6], W[7], Bb[7], W[8], Bb[8], W[9], Bb[9],
        outp, ntiles);
}

// round 12
// speedup vs baseline: 2.9865x; 1.0241x over previous
#include <cuda_runtime.h>
#include <cuda_bf16.h>
#include <cstdint>

typedef unsigned long long ull;
typedef uint32_t u32;

// ---------------- fragment arena byte offsets (256 B per 16x8 B-fragment) ----------------
static constexpr u32 TA_H = 0;      // towerA: Kp=48,Np=72 -> 3*9=27 frags
static constexpr u32 TA_L = 6912;
static constexpr u32 TB_H = 13824;  // towerB: Kp=112,Np=72 -> 7*9=63
static constexpr u32 TB_L = 29952;
static constexpr u32 L0_H = 46080;  // L0: Kp=160,Np=40 -> 10*5=50
static constexpr u32 L0_L = 58880;
static constexpr u32 L1_H = 71680;  // L1: Kp=48,Np=40 -> 15
static constexpr u32 L1_L = 75520;
static constexpr u32 L2_H = 79360;  // L2: Kp=48,Np=24 -> 9
static constexpr u32 L2_L = 81664;
static constexpr u32 L3_H = 83968;  // L3-6: Kp=32,Np=24 -> 6
static constexpr u32 L3_L = 85504;
static constexpr u32 L4_H = 87040;
static constexpr u32 L4_L = 88576;
static constexpr u32 L5_H = 90112;
static constexpr u32 L5_L = 91648;
static constexpr u32 L6_H = 93184;
static constexpr u32 L6_L = 94720;
static constexpr u32 L7_H = 96256;  // L7: Kp=32,Np=8 -> 2
static constexpr u32 L7_L = 96768;
static constexpr u32 BIAS_B = 97280;       // float arena
static constexpr u32 SMEM_TOTAL = 98816;   // 96.5 KB -> 2 CTAs/SM

// bias-arena float indices (all even -> float2-aligned)
static constexpr int JTA = 0, JTB = 72, J0 = 144, J1 = 184, J2 = 224, J3 = 248;
static constexpr int J4 = 272, J5 = 296, J6 = 320, J7 = 344;
static constexpr int JW8 = 352, JB8 = 368, JW9 = 370, JB9 = 372;  // W8 padded 8x2

__device__ __forceinline__ float lrelu(float x) { return fmaxf(x, 0.01f * x); }

// pack two f32 into bf16x2 (v0 -> low half)
__device__ __forceinline__ u32 cvtpack(float v0, float v1) {
    u32 r; asm("cvt.rn.bf16x2.f32 %0, %1, %2;" : "=r"(r) : "f"(v1), "f"(v0)); return r;
}
// hi/lo split pack: h = bf16(v), l = bf16(v - f32(h))
__device__ __forceinline__ void split_pack(float v0, float v1, u32& h, u32& l) {
    h = cvtpack(v0, v1);
    float h0 = __uint_as_float(h << 16);
    float h1 = __uint_as_float(h & 0xFFFF0000u);
    l = cvtpack(v0 - h0, v1 - h1);
}

__device__ __forceinline__ void mma16816(float& c0, float& c1, float& c2, float& c3,
                                         u32 a0, u32 a1, u32 a2, u32 a3, u32 b0, u32 b1) {
    asm volatile(
        "mma.sync.aligned.m16n8k16.row.col.f32.bf16.bf16.f32 "
        "{%0,%1,%2,%3}, {%4,%5,%6,%7}, {%8,%9}, {%0,%1,%2,%3};"
        : "+f"(c0), "+f"(c1), "+f"(c2), "+f"(c3)
        : "r"(a0), "r"(a1), "r"(a2), "r"(a3), "r"(b0), "r"(b1));
}

// D(nblk) -> A slot s: h[2s] from rows g (d0,d1), h[2s+1] from rows g+8 (d2,d3)
__device__ __forceinline__ void toslot(float d0, float d1, float d2, float d3,
                                       u32* h, u32* l, int s, bool act) {
    if (act) { d0 = lrelu(d0); d1 = lrelu(d1); d2 = lrelu(d2); d3 = lrelu(d3); }
    split_pack(d0, d1, h[2 * s + 0], l[2 * s + 0]);
    split_pack(d2, d3, h[2 * s + 1], l[2 * s + 1]);
}

// bounds-checked split load of 2 consecutive activations
__device__ __forceinline__ void ld_split(const float* __restrict__ p, int c, int Kreal,
                                         u32& h, u32& l) {
    float v0 = (c < Kreal) ? __ldg(p + c) : 0.0f;
    float v1 = (c + 1 < Kreal) ? __ldg(p + c + 1) : 0.0f;
    split_pack(v0, v1, h, l);
}

// One layer: D = bias + Ah*Wh + Al*Wh + Ah*Wl.
// RESTRUCTURED (R12): kb outer / nb inner -> all 4*NB accumulators live, so
// consecutive MMAs hit different accumulators (dependency distance = NB, was 1).
// Per-accumulator FP order is unchanged vs R11 (kb ascending: Ah,Al; then Ah*Wl)
// -> bitwise-identical result. Hi weights held in regs and reused by pass 2.
template <int KB, int NB>
__device__ __forceinline__ void layer(const u32* Ah, const u32* Al, const char* smc,
                                      u32 offH, u32 offL, int bidx, int lane, float* D) {
    const int t2 = (lane & 3) << 1;
    const float* biasp = reinterpret_cast<const float*>(smc + BIAS_B) + bidx;
    float acc[4 * NB];
#pragma unroll
    for (int nb = 0; nb < NB; nb++) {
        float2 bv = *reinterpret_cast<const float2*>(biasp + nb * 8 + t2);
        acc[4 * nb + 0] = bv.x; acc[4 * nb + 1] = bv.y;
        acc[4 * nb + 2] = bv.x; acc[4 * nb + 3] = bv.y;
    }
    const char* ph = smc + offH + (lane << 3);
    const char* pl = smc + offL + (lane << 3);
#pragma unroll
    for (int kb = 0; kb < KB; kb++) {
        u32 b0[NB], b1[NB];
#pragma unroll
        for (int nb = 0; nb < NB; nb++) {
            ull w = *reinterpret_cast<const ull*>(ph + (kb * NB + nb) * 256);
            b0[nb] = (u32)w; b1[nb] = (u32)(w >> 32);
            mma16816(acc[4 * nb + 0], acc[4 * nb + 1], acc[4 * nb + 2], acc[4 * nb + 3],
                     Ah[4 * kb], Ah[4 * kb + 1], Ah[4 * kb + 2], Ah[4 * kb + 3], b0[nb], b1[nb]);
        }
#pragma unroll
        for (int nb = 0; nb < NB; nb++)
            mma16816(acc[4 * nb + 0], acc[4 * nb + 1], acc[4 * nb + 2], acc[4 * nb + 3],
                     Al[4 * kb], Al[4 * kb + 1], Al[4 * kb + 2], Al[4 * kb + 3], b0[nb], b1[nb]);
    }
#pragma unroll
    for (int kb = 0; kb < KB; kb++) {
#pragma unroll
        for (int nb = 0; nb < NB; nb++) {
            ull w = *reinterpret_cast<const ull*>(pl + (kb * NB + nb) * 256);
            mma16816(acc[4 * nb + 0], acc[4 * nb + 1], acc[4 * nb + 2], acc[4 * nb + 3],
                     Ah[4 * kb], Ah[4 * kb + 1], Ah[4 * kb + 2], Ah[4 * kb + 3],
                     (u32)w, (u32)(w >> 32));
        }
    }
#pragma unroll
    for (int i = 0; i < 4 * NB; i++) D[i] = acc[i];
}

// W [K,N] row-major fp32 -> hi/lo B fragments. mode 1 = L0 concat row remap.
__device__ void prepW(char* smc, const float* __restrict__ W, int K, int N, int NBfr,
                      u32 offH, u32 offL, int tid, int mode) {
    for (int i = tid; i < K * N; i += 128) {
        int k = i / N, n = i - k * N;
        int kp = k;
        if (mode == 1) kp = (k < 68) ? k : ((k < 136) ? k + 4 : k + 8);
        // B frag layout: col n = lane>>2; k: b0 holds 2*(lane&3)+{0,1}, b1 = +8
        u32 fo = (u32)(((kp >> 4) * NBfr + (n >> 3)) << 8)
               + (u32)((((n & 7) << 2) | ((kp & 7) >> 1)) << 3)
               + (u32)(((kp >> 3) & 1) << 2)
               + (u32)((kp & 1) << 1);
        float v = W[i];
        __nv_bfloat16 h = __float2bfloat16(v);
        float lo = v - __bfloat162float(h);
        *reinterpret_cast<__nv_bfloat16*>(smc + offH + fo) = h;
        *reinterpret_cast<__nv_bfloat16*>(smc + offL + fo) = __float2bfloat16(lo);
    }
}

__global__ __launch_bounds__(128)
void Net_67954972557347_kernel(
    const float* __restrict__ a, const float* __restrict__ b, const float* __restrict__ meta,
    const float* __restrict__ Wa, const float* __restrict__ ba,
    const float* __restrict__ Wb, const float* __restrict__ bb,
    const float* __restrict__ W0, const float* __restrict__ B0,
    const float* __restrict__ W1, const float* __restrict__ B1,
    const float* __restrict__ W2, const float* __restrict__ B2,
    const float* __restrict__ W3, const float* __restrict__ B3,
    const float* __restrict__ W4, const float* __restrict__ B4,
    const float* __restrict__ W5, const float* __restrict__ B5,
    const float* __restrict__ W6, const float* __restrict__ B6,
    const float* __restrict__ W7, const float* __restrict__ B7,
    const float* __restrict__ W8, const float* __restrict__ B8,
    const float* __restrict__ W9, const float* __restrict__ B9,
    float* __restrict__ outp, int ntiles)
{
    extern __shared__ char smc[];
    const int tid = threadIdx.x, lane = tid & 31, warp = tid >> 5;

    // zero arenas (pads stay zero)
    for (u32 o = (u32)tid * 16; o < SMEM_TOTAL; o += 128 * 16)
        *reinterpret_cast<uint4*>(smc + o) = make_uint4(0, 0, 0, 0);
    __syncthreads();

    prepW(smc, Wa, 45, 68, 9, TA_H, TA_L, tid, 0);
    prepW(smc, Wb, 102, 68, 9, TB_H, TB_L, tid, 0);
    prepW(smc, W0, 140, 34, 5, L0_H, L0_L, tid, 1);
    prepW(smc, W1, 34, 34, 5, L1_H, L1_L, tid, 0);
    prepW(smc, W2, 34, 20, 3, L2_H, L2_L, tid, 0);
    prepW(smc, W3, 20, 20, 3, L3_H, L3_L, tid, 0);
    prepW(smc, W4, 20, 20, 3, L4_H, L4_L, tid, 0);
    prepW(smc, W5, 20, 20, 3, L5_H, L5_L, tid, 0);
    prepW(smc, W6, 20, 20, 3, L6_H, L6_L, tid, 0);
    prepW(smc, W7, 20, 5, 1, L7_H, L7_L, tid, 0);
    float* bs = reinterpret_cast<float*>(smc + BIAS_B);
    if (tid < 68) { bs[JTA + tid] = ba[tid]; bs[JTB + tid] = bb[tid]; }
    if (tid < 34) { bs[J0 + tid] = B0[tid]; bs[J1 + tid] = B1[tid]; }
    if (tid < 20) {
        bs[J2 + tid] = B2[tid]; bs[J3 + tid] = B3[tid]; bs[J4 + tid] = B4[tid];
        bs[J5 + tid] = B5[tid]; bs[J6 + tid] = B6[tid];
    }
    if (tid < 5)  bs[J7 + tid] = B7[tid];
    if (tid < 10) bs[JW8 + tid] = W8[tid];       // [k*2+n], rows 5-7 stay 0
    if (tid < 2)  { bs[JB8 + tid] = B8[tid]; bs[JW9 + tid] = W9[tid]; }
    if (tid == 0) bs[JB9] = B9[0];
    __syncthreads();

    const int t2 = (lane & 3) << 1;

    for (int tile = blockIdx.x * 4 + warp; tile < ntiles; tile += gridDim.x * 4) {
        const int r0 = tile * 16 + (lane >> 2), r1 = r0 + 8;
        u32 h0[40], l0[40];   // layer-0 A fragments (20 slots x 2)

        {   // tower A: K=45(pad48), N=72 -> slots 0..8
            u32 fh[12], fl[12];
            const float* p0 = a + (size_t)r0 * 45;
            const float* p1 = a + (size_t)r1 * 45;
#pragma unroll
            for (int kb = 0; kb < 3; kb++) {
                int c = kb * 16 + t2;
                ld_split(p0, c, 45, fh[4 * kb + 0], fl[4 * kb + 0]);
                ld_split(p1, c, 45, fh[4 * kb + 1], fl[4 * kb + 1]);
                ld_split(p0, c + 8, 45, fh[4 * kb + 2], fl[4 * kb + 2]);
                ld_split(p1, c + 8, 45, fh[4 * kb + 3], fl[4 * kb + 3]);
            }
            float D[36];
            layer<3, 9>(fh, fl, smc, TA_H, TA_L, JTA, lane, D);
#pragma unroll
            for (int nb = 0; nb < 9; nb++)
                toslot(D[4 * nb], D[4 * nb + 1], D[4 * nb + 2], D[4 * nb + 3], h0, l0, nb, true);
        }
        {   // tower B: K=102(pad112), N=72 -> slots 9..17
            u32 fh[28], fl[28];
            const float* p0 = b + (size_t)r0 * 102;
            const float* p1 = b + (size_t)r1 * 102;
#pragma unroll
            for (int kb = 0; kb < 7; kb++) {
                int c = kb * 16 + t2;
                ld_split(p0, c, 102, fh[4 * kb + 0], fl[4 * kb + 0]);
                ld_split(p1, c, 102, fh[4 * kb + 1], fl[4 * kb + 1]);
                ld_split(p0, c + 8, 102, fh[4 * kb + 2], fl[4 * kb + 2]);
                ld_split(p1, c + 8, 102, fh[4 * kb + 3], fl[4 * kb + 3]);
            }
            float D[36];
            layer<7, 9>(fh, fl, smc, TB_H, TB_L, JTB, lane, D);
#pragma unroll
            for (int nb = 0; nb < 9; nb++)
                toslot(D[4 * nb], D[4 * nb + 1], D[4 * nb + 2], D[4 * nb + 3], h0, l0, 9 + nb, true);
        }
        {   // meta -> slot 18 (cols 144-151; no lrelu), slot 19 zero
            float m0x = 0, m0y = 0, m1x = 0, m1y = 0;
            if (t2 < 4) {
                float2 u = *reinterpret_cast<const float2*>(meta + (size_t)r0 * 4 + t2);
                float2 v = *reinterpret_cast<const float2*>(meta + (size_t)r1 * 4 + t2);
                m0x = u.x; m0y = u.y; m1x = v.x; m1y = v.y;
            }
            toslot(m0x, m0y, m1x, m1y, h0, l0, 18, false);
            h0[38] = 0; h0[39] = 0; l0[38] = 0; l0[39] = 0;
        }

        u32 h1[12], l1[12];
        {   // L0: K=160, N=40
            float D[20];
            layer<10, 5>(h0, l0, smc, L0_H, L0_L, J0, lane, D);
#pragma unroll
            for (int nb = 0; nb < 5; nb++)
                toslot(D[4 * nb], D[4 * nb + 1], D[4 * nb + 2], D[4 * nb + 3], h1, l1, nb, true);
            h1[10] = 0; h1[11] = 0; l1[10] = 0; l1[11] = 0;
        }
        {   // L1: K=48, N=40
            float D[20];
            layer<3, 5>(h1, l1, smc, L1_H, L1_L, J1, lane, D);
#pragma unroll
            for (int nb = 0; nb < 5; nb++)
                toslot(D[4 * nb], D[4 * nb + 1], D[4 * nb + 2], D[4 * nb + 3], h1, l1, nb, true);
            h1[10] = 0; h1[11] = 0; l1[10] = 0; l1[11] = 0;
        }
        {   // L2: K=48, N=24
            float D[12];
            layer<3, 3>(h1, l1, smc, L2_H, L2_L, J2, lane, D);
#pragma unroll
            for (int nb = 0; nb < 3; nb++)
                toslot(D[4 * nb], D[4 * nb + 1], D[4 * nb + 2], D[4 * nb + 3], h1, l1, nb, true);
            h1[6] = 0; h1[7] = 0; l1[6] = 0; l1[7] = 0;
        }
        // L3..L6: K=32, N=24
        const u32 lh[4] = { L3_H, L4_H, L5_H, L6_H };
        const u32 ll[4] = { L3_L, L4_L, L5_L, L6_L };
        const int lj[4] = { J3, J4, J5, J6 };
#pragma unroll
        for (int L = 0; L < 4; L++) {
            float D[12];
            layer<2, 3>(h1, l1, smc, lh[L], ll[L], lj[L], lane, D);
#pragma unroll
            for (int nb = 0; nb < 3; nb++)
                toslot(D[4 * nb], D[4 * nb + 1], D[4 * nb + 2], D[4 * nb + 3], h1, l1, nb, true);
            h1[6] = 0; h1[7] = 0; l1[6] = 0; l1[7] = 0;
        }
        // L7: K=32, N=8
        float D7[4];
        layer<2, 1>(h1, l1, smc, L7_H, L7_L, J7, lane, D7);
        float v0 = lrelu(D7[0]), v1 = lrelu(D7[1]), v2 = lrelu(D7[2]), v3 = lrelu(D7[3]);

        // L8 (5->2) + L9 (2->1) scalar; 4-lane butterfly per row group
        float w8a0 = bs[JW8 + t2 * 2 + 0], w8b0 = bs[JW8 + t2 * 2 + 1];
        float w8a1 = bs[JW8 + (t2 + 1) * 2 + 0], w8b1 = bs[JW8 + (t2 + 1) * 2 + 1];
        float pa0 = fmaf(v0, w8a0, v1 * w8a1), pb0 = fmaf(v0, w8b0, v1 * w8b1);
        float pa1 = fmaf(v2, w8a0, v3 * w8a1), pb1 = fmaf(v2, w8b0, v3 * w8b1);
        pa0 += __shfl_xor_sync(0xFFFFFFFFu, pa0, 1); pa0 += __shfl_xor_sync(0xFFFFFFFFu, pa0, 2);
        pb0 += __shfl_xor_sync(0xFFFFFFFFu, pb0, 1); pb0 += __shfl_xor_sync(0xFFFFFFFFu, pb0, 2);
        pa1 += __shfl_xor_sync(0xFFFFFFFFu, pa1, 1); pa1 += __shfl_xor_sync(0xFFFFFFFFu, pa1, 2);
        pb1 += __shfl_xor_sync(0xFFFFFFFFu, pb1, 1); pb1 += __shfl_xor_sync(0xFFFFFFFFu, pb1, 2);
        float w90 = bs[JW9 + 0], w91 = bs[JW9 + 1], b9v = bs[JB9];
        float c8a = lrelu(pa0 + bs[JB8 + 0]), c8b = lrelu(pb0 + bs[JB8 + 1]);
        float o0 = lrelu(fmaf(c8a, w90, fmaf(c8b, w91, b9v)));
        c8a = lrelu(pa1 + bs[JB8 + 0]); c8b = lrelu(pb1 + bs[JB8 + 1]);
        float o1 = lrelu(fmaf(c8a, w90, fmaf(c8b, w91, b9v)));
        if ((lane & 3) == 0) { outp[r0] = o0; outp[r1] = o1; }
    }
}

extern "C" void kernel_launch(void* const* d_in, const int* in_sizes, int n_in,
                              void* d_out, int out_size) {
    const float* a    = (const float*)d_in[0];
    const float* b    = (const float*)d_in[1];
    const float* meta = (const float*)d_in[2];
    const float* Wa   = (const float*)d_in[3];
    const float* ba   = (const float*)d_in[4];
    const float* Wb   = (const float*)d_in[5];
    const float* bb   = (const float*)d_in[6];
    const float* W[10], *Bb[10];
    for (int i = 0; i < 10; i++) {
        W[i]  = (const float*)d_in[7 + 2 * i];
        Bb[i] = (const float*)d_in[8 + 2 * i];
    }
    float* outp = (float*)d_out;
    const int nrows = in_sizes[0] / 45;
    const int ntiles = nrows / 16;   // 16384

    cudaFuncSetAttribute(Net_67954972557347_kernel,
                         cudaFuncAttributeMaxDynamicSharedMemorySize, SMEM_TOTAL);

    // 96.5 KB smem -> 2 CTAs/SM; 128 threads = 4 independent warps per CTA.
    Net_67954972557347_kernel<<<296, 128, SMEM_TOTAL>>>(
        a, b, meta, Wa, ba, Wb, bb,
        W[0], Bb[0], W[1], Bb[1], W[2], Bb[2], W[3], Bb[3], W[4], Bb[4],
        W[5], Bb[5], W[6], Bb[6], W[7], Bb[7], W[8], Bb[8], W[9], Bb[9],
        outp, ntiles);
}

// round 13
// speedup vs baseline: 3.3451x; 1.1200x over previous
#include <cuda_runtime.h>
#include <cuda_bf16.h>
#include <cstdint>

typedef unsigned long long ull;
typedef uint32_t u32;

// ---------------- fragment arena byte offsets (256 B per 16x8 B-fragment) ----------------
static constexpr u32 TA_H = 0;      // towerA: Kp=48,Np=72 -> 3*9=27 frags
static constexpr u32 TA_L = 6912;
static constexpr u32 TB_H = 13824;  // towerB: Kp=112,Np=72 -> 7*9=63
static constexpr u32 TB_L = 29952;
static constexpr u32 L0_H = 46080;  // L0: Kp=160,Np=40 -> 10*5=50
static constexpr u32 L0_L = 58880;
static constexpr u32 L1_H = 71680;  // L1: Kp=48,Np=40 -> 15
static constexpr u32 L1_L = 75520;
static constexpr u32 L2_H = 79360;  // L2: Kp=48,Np=24 -> 9
static constexpr u32 L2_L = 81664;
static constexpr u32 L3_H = 83968;  // L3-6: Kp=32,Np=24 -> 6
static constexpr u32 L3_L = 85504;
static constexpr u32 L4_H = 87040;
static constexpr u32 L4_L = 88576;
static constexpr u32 L5_H = 90112;
static constexpr u32 L5_L = 91648;
static constexpr u32 L6_H = 93184;
static constexpr u32 L6_L = 94720;
static constexpr u32 L7_H = 96256;  // L7: Kp=32,Np=8 -> 2
static constexpr u32 L7_L = 96768;
static constexpr u32 BIAS_B = 97280;       // float arena
static constexpr u32 SMEM_TOTAL = 98816;   // 96.5 KB; 1 CTA/SM (384 threads)

// bias-arena float indices (all even -> float2-aligned)
static constexpr int JTA = 0, JTB = 72, J0 = 144, J1 = 184, J2 = 224, J3 = 248;
static constexpr int J4 = 272, J5 = 296, J6 = 320, J7 = 344;
static constexpr int JW8 = 352, JB8 = 368, JW9 = 370, JB9 = 372;  // W8 padded 8x2

__device__ int g_ctr;
__global__ void reset_ctr_kernel() { g_ctr = 0; }

__device__ __forceinline__ float lrelu(float x) { return fmaxf(x, 0.01f * x); }

// pack two f32 into bf16x2 (v0 -> low half)
__device__ __forceinline__ u32 cvtpack(float v0, float v1) {
    u32 r; asm("cvt.rn.bf16x2.f32 %0, %1, %2;" : "=r"(r) : "f"(v1), "f"(v0)); return r;
}
// hi/lo split pack: h = bf16(v), l = bf16(v - f32(h))
__device__ __forceinline__ void split_pack(float v0, float v1, u32& h, u32& l) {
    h = cvtpack(v0, v1);
    float h0 = __uint_as_float(h << 16);
    float h1 = __uint_as_float(h & 0xFFFF0000u);
    l = cvtpack(v0 - h0, v1 - h1);
}

__device__ __forceinline__ void mma16816(float& c0, float& c1, float& c2, float& c3,
                                         u32 a0, u32 a1, u32 a2, u32 a3, u32 b0, u32 b1) {
    asm volatile(
        "mma.sync.aligned.m16n8k16.row.col.f32.bf16.bf16.f32 "
        "{%0,%1,%2,%3}, {%4,%5,%6,%7}, {%8,%9}, {%0,%1,%2,%3};"
        : "+f"(c0), "+f"(c1), "+f"(c2), "+f"(c3)
        : "r"(a0), "r"(a1), "r"(a2), "r"(a3), "r"(b0), "r"(b1));
}

// D(nblk) -> A slot s
__device__ __forceinline__ void toslot(float d0, float d1, float d2, float d3,
                                       u32* h, u32* l, int s, bool act) {
    if (act) { d0 = lrelu(d0); d1 = lrelu(d1); d2 = lrelu(d2); d3 = lrelu(d3); }
    split_pack(d0, d1, h[2 * s + 0], l[2 * s + 0]);
    split_pack(d2, d3, h[2 * s + 1], l[2 * s + 1]);
}

// bounds-checked split load of 2 consecutive activations (scalar path)
__device__ __forceinline__ void ld_split(const float* __restrict__ p, int c, int Kreal,
                                         u32& h, u32& l) {
    float v0 = (c < Kreal) ? __ldg(p + c) : 0.0f;
    float v1 = (c + 1 < Kreal) ? __ldg(p + c + 1) : 0.0f;
    split_pack(v0, v1, h, l);
}
// float2 path for rows with even stride and even c (8B-aligned); Kreal even
__device__ __forceinline__ void ld_split2(const float* __restrict__ p, int c, int Kreal,
                                          u32& h, u32& l) {
    float v0 = 0.0f, v1 = 0.0f;
    if (c + 1 < Kreal) {
        float2 v = __ldg(reinterpret_cast<const float2*>(p + c));
        v0 = v.x; v1 = v.y;
    }
    split_pack(v0, v1, h, l);
}

// One layer: D = bias + Ah*Wh + Al*Wh + Ah*Wl. kb outer / nb inner (R12 structure).
template <int KB, int NB>
__device__ __forceinline__ void layer(const u32* Ah, const u32* Al, const char* smc,
                                      u32 offH, u32 offL, int bidx, int lane, float* D) {
    const int t2 = (lane & 3) << 1;
    const float* biasp = reinterpret_cast<const float*>(smc + BIAS_B) + bidx;
    float acc[4 * NB];
#pragma unroll
    for (int nb = 0; nb < NB; nb++) {
        float2 bv = *reinterpret_cast<const float2*>(biasp + nb * 8 + t2);
        acc[4 * nb + 0] = bv.x; acc[4 * nb + 1] = bv.y;
        acc[4 * nb + 2] = bv.x; acc[4 * nb + 3] = bv.y;
    }
    const char* ph = smc + offH + (lane << 3);
    const char* pl = smc + offL + (lane << 3);
#pragma unroll
    for (int kb = 0; kb < KB; kb++) {
        u32 b0[NB], b1[NB];
#pragma unroll
        for (int nb = 0; nb < NB; nb++) {
            ull w = *reinterpret_cast<const ull*>(ph + (kb * NB + nb) * 256);
            b0[nb] = (u32)w; b1[nb] = (u32)(w >> 32);
            mma16816(acc[4 * nb + 0], acc[4 * nb + 1], acc[4 * nb + 2], acc[4 * nb + 3],
                     Ah[4 * kb], Ah[4 * kb + 1], Ah[4 * kb + 2], Ah[4 * kb + 3], b0[nb], b1[nb]);
        }
#pragma unroll
        for (int nb = 0; nb < NB; nb++)
            mma16816(acc[4 * nb + 0], acc[4 * nb + 1], acc[4 * nb + 2], acc[4 * nb + 3],
                     Al[4 * kb], Al[4 * kb + 1], Al[4 * kb + 2], Al[4 * kb + 3], b0[nb], b1[nb]);
    }
#pragma unroll
    for (int kb = 0; kb < KB; kb++) {
#pragma unroll
        for (int nb = 0; nb < NB; nb++) {
            ull w = *reinterpret_cast<const ull*>(pl + (kb * NB + nb) * 256);
            mma16816(acc[4 * nb + 0], acc[4 * nb + 1], acc[4 * nb + 2], acc[4 * nb + 3],
                     Ah[4 * kb], Ah[4 * kb + 1], Ah[4 * kb + 2], Ah[4 * kb + 3],
                     (u32)w, (u32)(w >> 32));
        }
    }
#pragma unroll
    for (int i = 0; i < 4 * NB; i++) D[i] = acc[i];
}

// W [K,N] row-major fp32 -> hi/lo B fragments. mode 1 = L0 concat row remap.
__device__ void prepW(char* smc, const float* __restrict__ W, int K, int N, int NBfr,
                      u32 offH, u32 offL, int tid, int nt, int mode) {
    for (int i = tid; i < K * N; i += nt) {
        int k = i / N, n = i - k * N;
        int kp = k;
        if (mode == 1) kp = (k < 68) ? k : ((k < 136) ? k + 4 : k + 8);
        u32 fo = (u32)(((kp >> 4) * NBfr + (n >> 3)) << 8)
               + (u32)((((n & 7) << 2) | ((kp & 7) >> 1)) << 3)
               + (u32)(((kp >> 3) & 1) << 2)
               + (u32)((kp & 1) << 1);
        float v = W[i];
        __nv_bfloat16 h = __float2bfloat16(v);
        float lo = v - __bfloat162float(h);
        *reinterpret_cast<__nv_bfloat16*>(smc + offH + fo) = h;
        *reinterpret_cast<__nv_bfloat16*>(smc + offL + fo) = __float2bfloat16(lo);
    }
}

__global__ __launch_bounds__(384)
void Net_67954972557347_kernel(
    const float* __restrict__ a, const float* __restrict__ b, const float* __restrict__ meta,
    const float* __restrict__ Wa, const float* __restrict__ ba,
    const float* __restrict__ Wb, const float* __restrict__ bb,
    const float* __restrict__ W0, const float* __restrict__ B0,
    const float* __restrict__ W1, const float* __restrict__ B1,
    const float* __restrict__ W2, const float* __restrict__ B2,
    const float* __restrict__ W3, const float* __restrict__ B3,
    const float* __restrict__ W4, const float* __restrict__ B4,
    const float* __restrict__ W5, const float* __restrict__ B5,
    const float* __restrict__ W6, const float* __restrict__ B6,
    const float* __restrict__ W7, const float* __restrict__ B7,
    const float* __restrict__ W8, const float* __restrict__ B8,
    const float* __restrict__ W9, const float* __restrict__ B9,
    float* __restrict__ outp, int ntiles)
{
    extern __shared__ char smc[];
    const int tid = threadIdx.x, nt = blockDim.x, lane = tid & 31;

    // zero arenas (pads stay zero)
    for (u32 o = (u32)tid * 16; o < SMEM_TOTAL; o += (u32)nt * 16)
        *reinterpret_cast<uint4*>(smc + o) = make_uint4(0, 0, 0, 0);
    __syncthreads();

    prepW(smc, Wa, 45, 68, 9, TA_H, TA_L, tid, nt, 0);
    prepW(smc, Wb, 102, 68, 9, TB_H, TB_L, tid, nt, 0);
    prepW(smc, W0, 140, 34, 5, L0_H, L0_L, tid, nt, 1);
    prepW(smc, W1, 34, 34, 5, L1_H, L1_L, tid, nt, 0);
    prepW(smc, W2, 34, 20, 3, L2_H, L2_L, tid, nt, 0);
    prepW(smc, W3, 20, 20, 3, L3_H, L3_L, tid, nt, 0);
    prepW(smc, W4, 20, 20, 3, L4_H, L4_L, tid, nt, 0);
    prepW(smc, W5, 20, 20, 3, L5_H, L5_L, tid, nt, 0);
    prepW(smc, W6, 20, 20, 3, L6_H, L6_L, tid, nt, 0);
    prepW(smc, W7, 20, 5, 1, L7_H, L7_L, tid, nt, 0);
    float* bs = reinterpret_cast<float*>(smc + BIAS_B);
    if (tid < 68) { bs[JTA + tid] = ba[tid]; bs[JTB + tid] = bb[tid]; }
    if (tid < 34) { bs[J0 + tid] = B0[tid]; bs[J1 + tid] = B1[tid]; }
    if (tid < 20) {
        bs[J2 + tid] = B2[tid]; bs[J3 + tid] = B3[tid]; bs[J4 + tid] = B4[tid];
        bs[J5 + tid] = B5[tid]; bs[J6 + tid] = B6[tid];
    }
    if (tid < 5)  bs[J7 + tid] = B7[tid];
    if (tid < 10) bs[JW8 + tid] = W8[tid];
    if (tid < 2)  { bs[JB8 + tid] = B8[tid]; bs[JW9 + tid] = W9[tid]; }
    if (tid == 0) bs[JB9] = B9[0];
    __syncthreads();

    const int t2 = (lane & 3) << 1;

    for (;;) {
        // warp-level work stealing: grab a 16-row tile
        int tile;
        if (lane == 0) tile = atomicAdd(&g_ctr, 1);
        tile = __shfl_sync(0xFFFFFFFFu, tile, 0);
        if (tile >= ntiles) break;

        const int r0 = tile * 16 + (lane >> 2), r1 = r0 + 8;
        u32 h0[40], l0[40];   // layer-0 A fragments (20 slots x 2)

        {   // tower A: K=45(pad48), N=72 -> slots 0..8 (odd stride: scalar loads)
            u32 fh[12], fl[12];
            const float* p0 = a + (size_t)r0 * 45;
            const float* p1 = a + (size_t)r1 * 45;
#pragma unroll
            for (int kb = 0; kb < 3; kb++) {
                int c = kb * 16 + t2;
                ld_split(p0, c, 45, fh[4 * kb + 0], fl[4 * kb + 0]);
                ld_split(p1, c, 45, fh[4 * kb + 1], fl[4 * kb + 1]);
                ld_split(p0, c + 8, 45, fh[4 * kb + 2], fl[4 * kb + 2]);
                ld_split(p1, c + 8, 45, fh[4 * kb + 3], fl[4 * kb + 3]);
            }
            float D[36];
            layer<3, 9>(fh, fl, smc, TA_H, TA_L, JTA, lane, D);
#pragma unroll
            for (int nb = 0; nb < 9; nb++)
                toslot(D[4 * nb], D[4 * nb + 1], D[4 * nb + 2], D[4 * nb + 3], h0, l0, nb, true);
        }
        {   // tower B: K=102(pad112), N=72 -> slots 9..17 (even stride: float2 loads)
            u32 fh[28], fl[28];
            const float* p0 = b + (size_t)r0 * 102;
            const float* p1 = b + (size_t)r1 * 102;
#pragma unroll
            for (int kb = 0; kb < 7; kb++) {
                int c = kb * 16 + t2;
                ld_split2(p0, c, 102, fh[4 * kb + 0], fl[4 * kb + 0]);
                ld_split2(p1, c, 102, fh[4 * kb + 1], fl[4 * kb + 1]);
                ld_split2(p0, c + 8, 102, fh[4 * kb + 2], fl[4 * kb + 2]);
                ld_split2(p1, c + 8, 102, fh[4 * kb + 3], fl[4 * kb + 3]);
            }
            float D[36];
            layer<7, 9>(fh, fl, smc, TB_H, TB_L, JTB, lane, D);
#pragma unroll
            for (int nb = 0; nb < 9; nb++)
                toslot(D[4 * nb], D[4 * nb + 1], D[4 * nb + 2], D[4 * nb + 3], h0, l0, 9 + nb, true);
        }
        {   // meta -> slot 18 (cols 144-151; no lrelu), slot 19 zero
            float m0x = 0, m0y = 0, m1x = 0, m1y = 0;
            if (t2 < 4) {
                float2 u = *reinterpret_cast<const float2*>(meta + (size_t)r0 * 4 + t2);
                float2 v = *reinterpret_cast<const float2*>(meta + (size_t)r1 * 4 + t2);
                m0x = u.x; m0y = u.y; m1x = v.x; m1y = v.y;
            }
            toslot(m0x, m0y, m1x, m1y, h0, l0, 18, false);
            h0[38] = 0; h0[39] = 0; l0[38] = 0; l0[39] = 0;
        }

        u32 h1[12], l1[12];
        {   // L0: K=160, N=40
            float D[20];
            layer<10, 5>(h0, l0, smc, L0_H, L0_L, J0, lane, D);
#pragma unroll
            for (int nb = 0; nb < 5; nb++)
                toslot(D[4 * nb], D[4 * nb + 1], D[4 * nb + 2], D[4 * nb + 3], h1, l1, nb, true);
            h1[10] = 0; h1[11] = 0; l1[10] = 0; l1[11] = 0;
        }
        {   // L1: K=48, N=40
            float D[20];
            layer<3, 5>(h1, l1, smc, L1_H, L1_L, J1, lane, D);
#pragma unroll
            for (int nb = 0; nb < 5; nb++)
                toslot(D[4 * nb], D[4 * nb + 1], D[4 * nb + 2], D[4 * nb + 3], h1, l1, nb, true);
            h1[10] = 0; h1[11] = 0; l1[10] = 0; l1[11] = 0;
        }
        {   // L2: K=48, N=24
            float D[12];
            layer<3, 3>(h1, l1, smc, L2_H, L2_L, J2, lane, D);
#pragma unroll
            for (int nb = 0; nb < 3; nb++)
                toslot(D[4 * nb], D[4 * nb + 1], D[4 * nb + 2], D[4 * nb + 3], h1, l1, nb, true);
            h1[6] = 0; h1[7] = 0; l1[6] = 0; l1[7] = 0;
        }
        // L3..L6: K=32, N=24
        const u32 lh[4] = { L3_H, L4_H, L5_H, L6_H };
        const u32 ll[4] = { L3_L, L4_L, L5_L, L6_L };
        const int lj[4] = { J3, J4, J5, J6 };
#pragma unroll
        for (int L = 0; L < 4; L++) {
            float D[12];
            layer<2, 3>(h1, l1, smc, lh[L], ll[L], lj[L], lane, D);
#pragma unroll
            for (int nb = 0; nb < 3; nb++)
                toslot(D[4 * nb], D[4 * nb + 1], D[4 * nb + 2], D[4 * nb + 3], h1, l1, nb, true);
            h1[6] = 0; h1[7] = 0; l1[6] = 0; l1[7] = 0;
        }
        // L7: K=32, N=8
        float D7[4];
        layer<2, 1>(h1, l1, smc, L7_H, L7_L, J7, lane, D7);
        float v0 = lrelu(D7[0]), v1 = lrelu(D7[1]), v2 = lrelu(D7[2]), v3 = lrelu(D7[3]);

        // L8 (5->2) + L9 (2->1) scalar; 4-lane butterfly per row group
        float w8a0 = bs[JW8 + t2 * 2 + 0], w8b0 = bs[JW8 + t2 * 2 + 1];
        float w8a1 = bs[JW8 + (t2 + 1) * 2 + 0], w8b1 = bs[JW8 + (t2 + 1) * 2 + 1];
        float pa0 = fmaf(v0, w8a0, v1 * w8a1), pb0 = fmaf(v0, w8b0, v1 * w8b1);
        float pa1 = fmaf(v2, w8a0, v3 * w8a1), pb1 = fmaf(v2, w8b0, v3 * w8b1);
        pa0 += __shfl_xor_sync(0xFFFFFFFFu, pa0, 1); pa0 += __shfl_xor_sync(0xFFFFFFFFu, pa0, 2);
        pb0 += __shfl_xor_sync(0xFFFFFFFFu, pb0, 1); pb0 += __shfl_xor_sync(0xFFFFFFFFu, pb0, 2);
        pa1 += __shfl_xor_sync(0xFFFFFFFFu, pa1, 1); pa1 += __shfl_xor_sync(0xFFFFFFFFu, pa1, 2);
        pb1 += __shfl_xor_sync(0xFFFFFFFFu, pb1, 1); pb1 += __shfl_xor_sync(0xFFFFFFFFu, pb1, 2);
        float w90 = bs[JW9 + 0], w91 = bs[JW9 + 1], b9v = bs[JB9];
        float c8a = lrelu(pa0 + bs[JB8 + 0]), c8b = lrelu(pb0 + bs[JB8 + 1]);
        float o0 = lrelu(fmaf(c8a, w90, fmaf(c8b, w91, b9v)));
        c8a = lrelu(pa1 + bs[JB8 + 0]); c8b = lrelu(pb1 + bs[JB8 + 1]);
        float o1 = lrelu(fmaf(c8a, w90, fmaf(c8b, w91, b9v)));
        if ((lane & 3) == 0) { outp[r0] = o0; outp[r1] = o1; }
    }
}

extern "C" void kernel_launch(void* const* d_in, const int* in_sizes, int n_in,
                              void* d_out, int out_size) {
    const float* a    = (const float*)d_in[0];
    const float* b    = (const float*)d_in[1];
    const float* meta = (const float*)d_in[2];
    const float* Wa   = (const float*)d_in[3];
    const float* ba   = (const float*)d_in[4];
    const float* Wb   = (const float*)d_in[5];
    const float* bb   = (const float*)d_in[6];
    const float* W[10], *Bb[10];
    for (int i = 0; i < 10; i++) {
        W[i]  = (const float*)d_in[7 + 2 * i];
        Bb[i] = (const float*)d_in[8 + 2 * i];
    }
    float* outp = (float*)d_out;
    const int nrows = in_sizes[0] / 45;
    const int ntiles = nrows / 16;   // 16384

    cudaFuncSetAttribute(Net_67954972557347_kernel,
                         cudaFuncAttributeMaxDynamicSharedMemorySize, SMEM_TOTAL);

    reset_ctr_kernel<<<1, 1>>>();
    // 96.5 KB smem, 1 CTA/SM x 384 threads = 12 warps; warp-level work stealing.
    Net_67954972557347_kernel<<<148, 384, SMEM_TOTAL>>>(
        a, b, meta, Wa, ba, Wb, bb,
        W[0], Bb[0], W[1], Bb[1], W[2], Bb[2], W[3], Bb[3], W[4], Bb[4],
        W[5], Bb[5], W[6], Bb[6], W[7], Bb[7], W[8], Bb[8], W[9], Bb[9],
        outp, ntiles);
}

// round 14
// speedup vs baseline: 3.6502x; 1.0912x over previous
#include <cuda_runtime.h>
#include <cuda_bf16.h>
#include <cstdint>

typedef unsigned long long ull;
typedef uint32_t u32;

// ---------------- fragment arena byte offsets (256 B per 16x8 B-fragment) ----------------
static constexpr u32 TA_H = 0;      // towerA: Kp=48,Np=72 -> 27 frags
static constexpr u32 TA_L = 6912;
static constexpr u32 TB_H = 13824;  // towerB: Kp=112,Np=72 -> 63
static constexpr u32 TB_L = 29952;
static constexpr u32 L0_H = 46080;  // L0: Kp=144,Np=40 -> 45 (arena sized for 50, fine)
static constexpr u32 L0_L = 58880;
static constexpr u32 L1_H = 71680;  // L1: Kp=48,Np=40 -> 15
static constexpr u32 L1_L = 75520;
static constexpr u32 L2_H = 79360;  // L2: Kp=48,Np=24 -> 9
static constexpr u32 L2_L = 81664;
static constexpr u32 L3_H = 83968;  // L3-6: Kp=32,Np=24 -> 6
static constexpr u32 L3_L = 85504;
static constexpr u32 L4_H = 87040;
static constexpr u32 L4_L = 88576;
static constexpr u32 L5_H = 90112;
static constexpr u32 L5_L = 91648;
static constexpr u32 L6_H = 93184;
static constexpr u32 L6_L = 94720;
static constexpr u32 L7_H = 96256;  // L7: Kp=32,Np=8 -> 2
static constexpr u32 L7_L = 96768;
static constexpr u32 BIAS_B = 97280;       // float arena
static constexpr u32 SMEM_TOTAL = 98816;   // 96.5 KB; 1 CTA/SM

// bias-arena float indices (all even -> float2-aligned)
static constexpr int JTA = 0, JTB = 72, J0 = 144, J1 = 184, J2 = 224, J3 = 248;
static constexpr int J4 = 272, J5 = 296, J6 = 320, J7 = 344;
static constexpr int JW8 = 352, JB8 = 368, JW9 = 370, JB9 = 372;  // W8 padded 8x2

__device__ int g_ctr;
__global__ void reset_ctr_kernel() { g_ctr = 0; }

__device__ __forceinline__ float lrelu(float x) { return fmaxf(x, 0.01f * x); }

__device__ __forceinline__ u32 cvtpack(float v0, float v1) {
    u32 r; asm("cvt.rn.bf16x2.f32 %0, %1, %2;" : "=r"(r) : "f"(v1), "f"(v0)); return r;
}
__device__ __forceinline__ void split_pack(float v0, float v1, u32& h, u32& l) {
    h = cvtpack(v0, v1);
    float h0 = __uint_as_float(h << 16);
    float h1 = __uint_as_float(h & 0xFFFF0000u);
    l = cvtpack(v0 - h0, v1 - h1);
}

__device__ __forceinline__ void mma16816(float& c0, float& c1, float& c2, float& c3,
                                         u32 a0, u32 a1, u32 a2, u32 a3, u32 b0, u32 b1) {
    asm volatile(
        "mma.sync.aligned.m16n8k16.row.col.f32.bf16.bf16.f32 "
        "{%0,%1,%2,%3}, {%4,%5,%6,%7}, {%8,%9}, {%0,%1,%2,%3};"
        : "+f"(c0), "+f"(c1), "+f"(c2), "+f"(c3)
        : "r"(a0), "r"(a1), "r"(a2), "r"(a3), "r"(b0), "r"(b1));
}

// D(nblk) -> A slot s (for dense-layer chaining)
__device__ __forceinline__ void toslot(float d0, float d1, float d2, float d3,
                                       u32* h, u32* l, int s, bool act) {
    if (act) { d0 = lrelu(d0); d1 = lrelu(d1); d2 = lrelu(d2); d3 = lrelu(d3); }
    split_pack(d0, d1, h[2 * s + 0], l[2 * s + 0]);
    split_pack(d2, d3, h[2 * s + 1], l[2 * s + 1]);
}

// bounds-checked split loads
__device__ __forceinline__ void ld_split(const float* __restrict__ p, int c, int Kreal,
                                         u32& h, u32& l) {
    float v0 = (c < Kreal) ? __ldg(p + c) : 0.0f;
    float v1 = (c + 1 < Kreal) ? __ldg(p + c + 1) : 0.0f;
    split_pack(v0, v1, h, l);
}
__device__ __forceinline__ void ld_split2(const float* __restrict__ p, int c, int Kreal,
                                          u32& h, u32& l) {
    float v0 = 0.0f, v1 = 0.0f;
    if (c + 1 < Kreal) {
        float2 v = __ldg(reinterpret_cast<const float2*>(p + c));
        v0 = v.x; v1 = v.y;
    }
    split_pack(v0, v1, h, l);
}
template <int VEC>
__device__ __forceinline__ void ld_frag(const float* p0, const float* p1, int c, int Kreal,
                                        u32* fh, u32* fl) {
    if (VEC) {
        ld_split2(p0, c, Kreal, fh[0], fl[0]);
        ld_split2(p1, c, Kreal, fh[1], fl[1]);
        ld_split2(p0, c + 8, Kreal, fh[2], fl[2]);
        ld_split2(p1, c + 8, Kreal, fh[3], fl[3]);
    } else {
        ld_split(p0, c, Kreal, fh[0], fl[0]);
        ld_split(p1, c, Kreal, fh[1], fl[1]);
        ld_split(p0, c + 8, Kreal, fh[2], fl[2]);
        ld_split(p1, c + 8, Kreal, fh[3], fl[3]);
    }
}

// Streaming tower layer (N=72, NB=9): A frags loaded per-kb (double-buffered),
// 3 passes per kb (Ah*Wh, Al*Wh, Ah*Wl).
template <int KB, int VEC>
__device__ void tower_layer(const float* __restrict__ p0, const float* __restrict__ p1,
                            int Kreal, const char* smc, u32 offH, u32 offL, int bidx,
                            int lane, float* D) {
    const int t2 = (lane & 3) << 1;
    const float* biasp = reinterpret_cast<const float*>(smc + BIAS_B) + bidx;
    float acc[36];
#pragma unroll
    for (int nb = 0; nb < 9; nb++) {
        float2 bv = *reinterpret_cast<const float2*>(biasp + nb * 8 + t2);
        acc[4 * nb + 0] = bv.x; acc[4 * nb + 1] = bv.y;
        acc[4 * nb + 2] = bv.x; acc[4 * nb + 3] = bv.y;
    }
    const char* ph = smc + offH + (lane << 3);
    const char* pl = smc + offL + (lane << 3);
    u32 cfh[4], cfl[4], nfh[4], nfl[4];
    ld_frag<VEC>(p0, p1, t2, Kreal, cfh, cfl);
#pragma unroll
    for (int kb = 0; kb < KB; kb++) {
        if (kb + 1 < KB) ld_frag<VEC>(p0, p1, (kb + 1) * 16 + t2, Kreal, nfh, nfl);
        u32 b0[9], b1[9];
#pragma unroll
        for (int nb = 0; nb < 9; nb++) {
            ull w = *reinterpret_cast<const ull*>(ph + (kb * 9 + nb) * 256);
            b0[nb] = (u32)w; b1[nb] = (u32)(w >> 32);
            mma16816(acc[4 * nb + 0], acc[4 * nb + 1], acc[4 * nb + 2], acc[4 * nb + 3],
                     cfh[0], cfh[1], cfh[2], cfh[3], b0[nb], b1[nb]);
        }
#pragma unroll
        for (int nb = 0; nb < 9; nb++)
            mma16816(acc[4 * nb + 0], acc[4 * nb + 1], acc[4 * nb + 2], acc[4 * nb + 3],
                     cfl[0], cfl[1], cfl[2], cfl[3], b0[nb], b1[nb]);
#pragma unroll
        for (int nb = 0; nb < 9; nb++) {
            ull w = *reinterpret_cast<const ull*>(pl + (kb * 9 + nb) * 256);
            mma16816(acc[4 * nb + 0], acc[4 * nb + 1], acc[4 * nb + 2], acc[4 * nb + 3],
                     cfh[0], cfh[1], cfh[2], cfh[3], (u32)w, (u32)(w >> 32));
        }
#pragma unroll
        for (int i = 0; i < 4; i++) { cfh[i] = nfh[i]; cfl[i] = nfl[i]; }
    }
#pragma unroll
    for (int i = 0; i < 36; i++) D[i] = acc[i];
}

// One L0 k-block (16 concat cols = slots 2kb,2kb+1) against rolling frag buffer sh/sl[4].
__device__ __forceinline__ void l0_kb(float* acc, const u32* sh, const u32* sl, int kb,
                                      const char* smc, int lane) {
    const char* ph = smc + L0_H + (lane << 3);
    const char* pl = smc + L0_L + (lane << 3);
    u32 b0[5], b1[5];
#pragma unroll
    for (int nb = 0; nb < 5; nb++) {
        ull w = *reinterpret_cast<const ull*>(ph + (kb * 5 + nb) * 256);
        b0[nb] = (u32)w; b1[nb] = (u32)(w >> 32);
        mma16816(acc[4 * nb + 0], acc[4 * nb + 1], acc[4 * nb + 2], acc[4 * nb + 3],
                 sh[0], sh[1], sh[2], sh[3], b0[nb], b1[nb]);
    }
#pragma unroll
    for (int nb = 0; nb < 5; nb++)
        mma16816(acc[4 * nb + 0], acc[4 * nb + 1], acc[4 * nb + 2], acc[4 * nb + 3],
                 sl[0], sl[1], sl[2], sl[3], b0[nb], b1[nb]);
#pragma unroll
    for (int nb = 0; nb < 5; nb++) {
        ull w = *reinterpret_cast<const ull*>(pl + (kb * 5 + nb) * 256);
        mma16816(acc[4 * nb + 0], acc[4 * nb + 1], acc[4 * nb + 2], acc[4 * nb + 3],
                 sh[0], sh[1], sh[2], sh[3], (u32)w, (u32)(w >> 32));
    }
}

// Dense layer (R12/13 structure) for L1..L7 chaining on register fragments.
template <int KB, int NB>
__device__ __forceinline__ void layer(const u32* Ah, const u32* Al, const char* smc,
                                      u32 offH, u32 offL, int bidx, int lane, float* D) {
    const int t2 = (lane & 3) << 1;
    const float* biasp = reinterpret_cast<const float*>(smc + BIAS_B) + bidx;
    float acc[4 * NB];
#pragma unroll
    for (int nb = 0; nb < NB; nb++) {
        float2 bv = *reinterpret_cast<const float2*>(biasp + nb * 8 + t2);
        acc[4 * nb + 0] = bv.x; acc[4 * nb + 1] = bv.y;
        acc[4 * nb + 2] = bv.x; acc[4 * nb + 3] = bv.y;
    }
    const char* ph = smc + offH + (lane << 3);
    const char* pl = smc + offL + (lane << 3);
#pragma unroll
    for (int kb = 0; kb < KB; kb++) {
        u32 b0[NB], b1[NB];
#pragma unroll
        for (int nb = 0; nb < NB; nb++) {
            ull w = *reinterpret_cast<const ull*>(ph + (kb * NB + nb) * 256);
            b0[nb] = (u32)w; b1[nb] = (u32)(w >> 32);
            mma16816(acc[4 * nb + 0], acc[4 * nb + 1], acc[4 * nb + 2], acc[4 * nb + 3],
                     Ah[4 * kb], Ah[4 * kb + 1], Ah[4 * kb + 2], Ah[4 * kb + 3], b0[nb], b1[nb]);
        }
#pragma unroll
        for (int nb = 0; nb < NB; nb++)
            mma16816(acc[4 * nb + 0], acc[4 * nb + 1], acc[4 * nb + 2], acc[4 * nb + 3],
                     Al[4 * kb], Al[4 * kb + 1], Al[4 * kb + 2], Al[4 * kb + 3], b0[nb], b1[nb]);
    }
#pragma unroll
    for (int kb = 0; kb < KB; kb++) {
#pragma unroll
        for (int nb = 0; nb < NB; nb++) {
            ull w = *reinterpret_cast<const ull*>(pl + (kb * NB + nb) * 256);
            mma16816(acc[4 * nb + 0], acc[4 * nb + 1], acc[4 * nb + 2], acc[4 * nb + 3],
                     Ah[4 * kb], Ah[4 * kb + 1], Ah[4 * kb + 2], Ah[4 * kb + 3],
                     (u32)w, (u32)(w >> 32));
        }
    }
#pragma unroll
    for (int i = 0; i < 4 * NB; i++) D[i] = acc[i];
}

// W [K,N] row-major fp32 -> hi/lo B fragments. mode 1 = L0 concat row remap (Kp=144).
__device__ void prepW(char* smc, const float* __restrict__ W, int K, int N, int NBfr,
                      u32 offH, u32 offL, int tid, int nt, int mode) {
    for (int i = tid; i < K * N; i += nt) {
        int k = i / N, n = i - k * N;
        int kp = k;
        if (mode == 1) kp = (k < 68) ? k : k + 4;  // towerA 0-67, towerB 72-139, meta 140-143
        u32 fo = (u32)(((kp >> 4) * NBfr + (n >> 3)) << 8)
               + (u32)((((n & 7) << 2) | ((kp & 7) >> 1)) << 3)
               + (u32)(((kp >> 3) & 1) << 2)
               + (u32)((kp & 1) << 1);
        float v = W[i];
        __nv_bfloat16 h = __float2bfloat16(v);
        float lo = v - __bfloat162float(h);
        *reinterpret_cast<__nv_bfloat16*>(smc + offH + fo) = h;
        *reinterpret_cast<__nv_bfloat16*>(smc + offL + fo) = __float2bfloat16(lo);
    }
}

__global__ __launch_bounds__(480)
void Net_67954972557347_kernel(
    const float* __restrict__ a, const float* __restrict__ b, const float* __restrict__ meta,
    const float* __restrict__ Wa, const float* __restrict__ ba,
    const float* __restrict__ Wb, const float* __restrict__ bb,
    const float* __restrict__ W0, const float* __restrict__ B0,
    const float* __restrict__ W1, const float* __restrict__ B1,
    const float* __restrict__ W2, const float* __restrict__ B2,
    const float* __restrict__ W3, const float* __restrict__ B3,
    const float* __restrict__ W4, const float* __restrict__ B4,
    const float* __restrict__ W5, const float* __restrict__ B5,
    const float* __restrict__ W6, const float* __restrict__ B6,
    const float* __restrict__ W7, const float* __restrict__ B7,
    const float* __restrict__ W8, const float* __restrict__ B8,
    const float* __restrict__ W9, const float* __restrict__ B9,
    float* __restrict__ outp, int ntiles)
{
    extern __shared__ char smc[];
    const int tid = threadIdx.x, nt = blockDim.x, lane = tid & 31;

    for (u32 o = (u32)tid * 16; o < SMEM_TOTAL; o += (u32)nt * 16)
        *reinterpret_cast<uint4*>(smc + o) = make_uint4(0, 0, 0, 0);
    __syncthreads();

    prepW(smc, Wa, 45, 68, 9, TA_H, TA_L, tid, nt, 0);
    prepW(smc, Wb, 102, 68, 9, TB_H, TB_L, tid, nt, 0);
    prepW(smc, W0, 140, 34, 5, L0_H, L0_L, tid, nt, 1);
    prepW(smc, W1, 34, 34, 5, L1_H, L1_L, tid, nt, 0);
    prepW(smc, W2, 34, 20, 3, L2_H, L2_L, tid, nt, 0);
    prepW(smc, W3, 20, 20, 3, L3_H, L3_L, tid, nt, 0);
    prepW(smc, W4, 20, 20, 3, L4_H, L4_L, tid, nt, 0);
    prepW(smc, W5, 20, 20, 3, L5_H, L5_L, tid, nt, 0);
    prepW(smc, W6, 20, 20, 3, L6_H, L6_L, tid, nt, 0);
    prepW(smc, W7, 20, 5, 1, L7_H, L7_L, tid, nt, 0);
    float* bs = reinterpret_cast<float*>(smc + BIAS_B);
    if (tid < 68) { bs[JTA + tid] = ba[tid]; bs[JTB + tid] = bb[tid]; }
    if (tid < 34) { bs[J0 + tid] = B0[tid]; bs[J1 + tid] = B1[tid]; }
    if (tid < 20) {
        bs[J2 + tid] = B2[tid]; bs[J3 + tid] = B3[tid]; bs[J4 + tid] = B4[tid];
        bs[J5 + tid] = B5[tid]; bs[J6 + tid] = B6[tid];
    }
    if (tid < 5)  bs[J7 + tid] = B7[tid];
    if (tid < 10) bs[JW8 + tid] = W8[tid];
    if (tid < 2)  { bs[JB8 + tid] = B8[tid]; bs[JW9 + tid] = W9[tid]; }
    if (tid == 0) bs[JB9] = B9[0];
    __syncthreads();

    const int t2 = (lane & 3) << 1;

    for (;;) {
        int tile;
        if (lane == 0) tile = atomicAdd(&g_ctr, 1);
        tile = __shfl_sync(0xFFFFFFFFu, tile, 0);
        if (tile >= ntiles) break;

        const int r0 = tile * 16 + (lane >> 2), r1 = r0 + 8;

        // L0 accumulator (fused) + rolling 2-slot fragment buffer
        float accL0[20];
#pragma unroll
        for (int nb = 0; nb < 5; nb++) {
            float2 bv = *reinterpret_cast<const float2*>(bs + J0 + nb * 8 + t2);
            accL0[4 * nb + 0] = bv.x; accL0[4 * nb + 1] = bv.y;
            accL0[4 * nb + 2] = bv.x; accL0[4 * nb + 3] = bv.y;
        }
        u32 sh[4], sl[4];

        {   // tower A (concat slots 0..8; fires L0 kb 0..3, slot 8 pending)
            float D[36];
            tower_layer<3, 0>(a + (size_t)r0 * 45, a + (size_t)r1 * 45, 45,
                              smc, TA_H, TA_L, JTA, lane, D);
#pragma unroll
            for (int nb = 0; nb < 9; nb++) {
                int half = nb & 1;
                float d0 = lrelu(D[4 * nb + 0]), d1 = lrelu(D[4 * nb + 1]);
                float d2 = lrelu(D[4 * nb + 2]), d3 = lrelu(D[4 * nb + 3]);
                split_pack(d0, d1, sh[2 * half + 0], sl[2 * half + 0]);
                split_pack(d2, d3, sh[2 * half + 1], sl[2 * half + 1]);
                if (half) l0_kb(accL0, sh, sl, nb >> 1, smc, lane);
            }
        }
        {   // tower B (concat slots 9..17; meta merged into slot 17 cols 4..7)
            float D[36];
            tower_layer<7, 1>(b + (size_t)r0 * 102, b + (size_t)r1 * 102, 102,
                              smc, TB_H, TB_L, JTB, lane, D);
#pragma unroll
            for (int nb = 0; nb < 8; nb++) {
                int half = (nb + 1) & 1;   // slot 9+nb
                float d0 = lrelu(D[4 * nb + 0]), d1 = lrelu(D[4 * nb + 1]);
                float d2 = lrelu(D[4 * nb + 2]), d3 = lrelu(D[4 * nb + 3]);
                split_pack(d0, d1, sh[2 * half + 0], sl[2 * half + 0]);
                split_pack(d2, d3, sh[2 * half + 1], sl[2 * half + 1]);
                if (half) l0_kb(accL0, sh, sl, (9 + nb) >> 1, smc, lane);
            }
            {   // nb=8 -> slot 17 (odd): cols 0-3 = towerB outs 64-67, cols 4-7 = meta (no lrelu)
                float e0, e1, e2, e3;
                if (t2 < 4) {
                    e0 = lrelu(D[32]); e1 = lrelu(D[33]);
                    e2 = lrelu(D[34]); e3 = lrelu(D[35]);
                } else {
                    float2 u = *reinterpret_cast<const float2*>(meta + (size_t)r0 * 4 + (t2 - 4));
                    float2 v = *reinterpret_cast<const float2*>(meta + (size_t)r1 * 4 + (t2 - 4));
                    e0 = u.x; e1 = u.y; e2 = v.x; e3 = v.y;
                }
                split_pack(e0, e1, sh[2], sl[2]);
                split_pack(e2, e3, sh[3], sl[3]);
                l0_kb(accL0, sh, sl, 8, smc, lane);
            }
        }

        // L0 outputs -> fragments for L1
        u32 h1[12], l1[12];
#pragma unroll
        for (int nb = 0; nb < 5; nb++)
            toslot(accL0[4 * nb], accL0[4 * nb + 1], accL0[4 * nb + 2], accL0[4 * nb + 3],
                   h1, l1, nb, true);
        h1[10] = 0; h1[11] = 0; l1[10] = 0; l1[11] = 0;

        {   // L1: K=48, N=40
            float D[20];
            layer<3, 5>(h1, l1, smc, L1_H, L1_L, J1, lane, D);
#pragma unroll
            for (int nb = 0; nb < 5; nb++)
                toslot(D[4 * nb], D[4 * nb + 1], D[4 * nb + 2], D[4 * nb + 3], h1, l1, nb, true);
            h1[10] = 0; h1[11] = 0; l1[10] = 0; l1[11] = 0;
        }
        {   // L2: K=48, N=24
            float D[12];
            layer<3, 3>(h1, l1, smc, L2_H, L2_L, J2, lane, D);
#pragma unroll
            for (int nb = 0; nb < 3; nb++)
                toslot(D[4 * nb], D[4 * nb + 1], D[4 * nb + 2], D[4 * nb + 3], h1, l1, nb, true);
            h1[6] = 0; h1[7] = 0; l1[6] = 0; l1[7] = 0;
        }
        const u32 lh[4] = { L3_H, L4_H, L5_H, L6_H };
        const u32 ll[4] = { L3_L, L4_L, L5_L, L6_L };
        const int lj[4] = { J3, J4, J5, J6 };
#pragma unroll
        for (int L = 0; L < 4; L++) {
            float D[12];
            layer<2, 3>(h1, l1, smc, lh[L], ll[L], lj[L], lane, D);
#pragma unroll
            for (int nb = 0; nb < 3; nb++)
                toslot(D[4 * nb], D[4 * nb + 1], D[4 * nb + 2], D[4 * nb + 3], h1, l1, nb, true);
            h1[6] = 0; h1[7] = 0; l1[6] = 0; l1[7] = 0;
        }
        // L7: K=32, N=8
        float D7[4];
        layer<2, 1>(h1, l1, smc, L7_H, L7_L, J7, lane, D7);
        float v0 = lrelu(D7[0]), v1 = lrelu(D7[1]), v2 = lrelu(D7[2]), v3 = lrelu(D7[3]);

        // L8 (5->2) + L9 (2->1) scalar; 4-lane butterfly per row group
        float w8a0 = bs[JW8 + t2 * 2 + 0], w8b0 = bs[JW8 + t2 * 2 + 1];
        float w8a1 = bs[JW8 + (t2 + 1) * 2 + 0], w8b1 = bs[JW8 + (t2 + 1) * 2 + 1];
        float pa0 = fmaf(v0, w8a0, v1 * w8a1), pb0 = fmaf(v0, w8b0, v1 * w8b1);
        float pa1 = fmaf(v2, w8a0, v3 * w8a1), pb1 = fmaf(v2, w8b0, v3 * w8b1);
        pa0 += __shfl_xor_sync(0xFFFFFFFFu, pa0, 1); pa0 += __shfl_xor_sync(0xFFFFFFFFu, pa0, 2);
        pb0 += __shfl_xor_sync(0xFFFFFFFFu, pb0, 1); pb0 += __shfl_xor_sync(0xFFFFFFFFu, pb0, 2);
        pa1 += __shfl_xor_sync(0xFFFFFFFFu, pa1, 1); pa1 += __shfl_xor_sync(0xFFFFFFFFu, pa1, 2);
        pb1 += __shfl_xor_sync(0xFFFFFFFFu, pb1, 1); pb1 += __shfl_xor_sync(0xFFFFFFFFu, pb1, 2);
        float w90 = bs[JW9 + 0], w91 = bs[JW9 + 1], b9v = bs[JB9];
        float c8a = lrelu(pa0 + bs[JB8 + 0]), c8b = lrelu(pb0 + bs[JB8 + 1]);
        float o0 = lrelu(fmaf(c8a, w90, fmaf(c8b, w91, b9v)));
        c8a = lrelu(pa1 + bs[JB8 + 0]); c8b = lrelu(pb1 + bs[JB8 + 1]);
        float o1 = lrelu(fmaf(c8a, w90, fmaf(c8b, w91, b9v)));
        if ((lane & 3) == 0) { outp[r0] = o0; outp[r1] = o1; }
    }
}

extern "C" void kernel_launch(void* const* d_in, const int* in_sizes, int n_in,
                              void* d_out, int out_size) {
    const float* a    = (const float*)d_in[0];
    const float* b    = (const float*)d_in[1];
    const float* meta = (const float*)d_in[2];
    const float* Wa   = (const float*)d_in[3];
    const float* ba   = (const float*)d_in[4];
    const float* Wb   = (const float*)d_in[5];
    const float* bb   = (const float*)d_in[6];
    const float* W[10], *Bb[10];
    for (int i = 0; i < 10; i++) {
        W[i]  = (const float*)d_in[7 + 2 * i];
        Bb[i] = (const float*)d_in[8 + 2 * i];
    }
    float* outp = (float*)d_out;
    const int nrows = in_sizes[0] / 45;
    const int ntiles = nrows / 16;   // 16384

    cudaFuncSetAttribute(Net_67954972557347_kernel,
                         cudaFuncAttributeMaxDynamicSharedMemorySize, SMEM_TOTAL);

    reset_ctr_kernel<<<1, 1>>>();
    // 96.5 KB smem, 1 CTA/SM x 480 threads = 15 warps; fused-L0 keeps regs ~<136.
    Net_67954972557347_kernel<<<148, 480, SMEM_TOTAL>>>(
        a, b, meta, Wa, ba, Wb, bb,
        W[0], Bb[0], W[1], Bb[1], W[2], Bb[2], W[3], Bb[3], W[4], Bb[4],
        W[5], Bb[5], W[6], Bb[6], W[7], Bb[7], W[8], Bb[8], W[9], Bb[9],
        outp, ntiles);
}

// round 16
// speedup vs baseline: 3.7497x; 1.0272x over previous
#include <cuda_runtime.h>
#include <cuda_bf16.h>
#include <cstdint>

typedef unsigned long long ull;
typedef uint32_t u32;

// ---------------- fragment arena byte offsets (256 B per 16x8 B-fragment) ----------------
static constexpr u32 TA_H = 0;      // towerA: Kp=48,Np=72 -> 27 frags
static constexpr u32 TA_L = 6912;
static constexpr u32 TB_H = 13824;  // towerB: Kp=112,Np=72 -> 63
static constexpr u32 TB_L = 29952;
static constexpr u32 L0_H = 46080;  // L0: Kp=144,Np=40 -> 45 (arena sized for 50, fine)
static constexpr u32 L0_L = 58880;
static constexpr u32 L1_H = 71680;  // L1: Kp=48,Np=40 -> 15
static constexpr u32 L1_L = 75520;
static constexpr u32 L2_H = 79360;  // L2: Kp=48,Np=24 -> 9
static constexpr u32 L2_L = 81664;
static constexpr u32 L3_H = 83968;  // L3-6: Kp=32,Np=24 -> 6
static constexpr u32 L3_L = 85504;
static constexpr u32 L4_H = 87040;
static constexpr u32 L4_L = 88576;
static constexpr u32 L5_H = 90112;
static constexpr u32 L5_L = 91648;
static constexpr u32 L6_H = 93184;
static constexpr u32 L6_L = 94720;
static constexpr u32 L7_H = 96256;  // L7: Kp=32,Np=8 -> 2
static constexpr u32 L7_L = 96768;
static constexpr u32 BIAS_B = 97280;       // float arena
static constexpr u32 SMEM_TOTAL = 98816;   // 96.5 KB; 1 CTA/SM

// bias-arena float indices (all even -> float2-aligned)
static constexpr int JTA = 0, JTB = 72, J0 = 144, J1 = 184, J2 = 224, J3 = 248;
static constexpr int J4 = 272, J5 = 296, J6 = 320, J7 = 344;
static constexpr int JW8 = 352, JB8 = 368, JW9 = 370, JB9 = 372;  // W8 padded 8x2

__device__ int g_ctr;
__global__ void reset_ctr_kernel() { g_ctr = 0; }

__device__ __forceinline__ float lrelu(float x) { return fmaxf(x, 0.01f * x); }

__device__ __forceinline__ u32 cvtpack(float v0, float v1) {
    u32 r; asm("cvt.rn.bf16x2.f32 %0, %1, %2;" : "=r"(r) : "f"(v1), "f"(v0)); return r;
}
__device__ __forceinline__ void split_pack(float v0, float v1, u32& h, u32& l) {
    h = cvtpack(v0, v1);
    float h0 = __uint_as_float(h << 16);
    float h1 = __uint_as_float(h & 0xFFFF0000u);
    l = cvtpack(v0 - h0, v1 - h1);
}

__device__ __forceinline__ void mma16816(float& c0, float& c1, float& c2, float& c3,
                                         u32 a0, u32 a1, u32 a2, u32 a3, u32 b0, u32 b1) {
    asm volatile(
        "mma.sync.aligned.m16n8k16.row.col.f32.bf16.bf16.f32 "
        "{%0,%1,%2,%3}, {%4,%5,%6,%7}, {%8,%9}, {%0,%1,%2,%3};"
        : "+f"(c0), "+f"(c1), "+f"(c2), "+f"(c3)
        : "r"(a0), "r"(a1), "r"(a2), "r"(a3), "r"(b0), "r"(b1));
}

// D(nblk) -> A slot s (for dense-layer chaining)
__device__ __forceinline__ void toslot(float d0, float d1, float d2, float d3,
                                       u32* h, u32* l, int s, bool act) {
    if (act) { d0 = lrelu(d0); d1 = lrelu(d1); d2 = lrelu(d2); d3 = lrelu(d3); }
    split_pack(d0, d1, h[2 * s + 0], l[2 * s + 0]);
    split_pack(d2, d3, h[2 * s + 1], l[2 * s + 1]);
}

// bounds-checked split loads
__device__ __forceinline__ void ld_split(const float* __restrict__ p, int c, int Kreal,
                                         u32& h, u32& l) {
    float v0 = (c < Kreal) ? __ldg(p + c) : 0.0f;
    float v1 = (c + 1 < Kreal) ? __ldg(p + c + 1) : 0.0f;
    split_pack(v0, v1, h, l);
}
__device__ __forceinline__ void ld_split2(const float* __restrict__ p, int c, int Kreal,
                                          u32& h, u32& l) {
    float v0 = 0.0f, v1 = 0.0f;
    if (c + 1 < Kreal) {
        float2 v = __ldg(reinterpret_cast<const float2*>(p + c));
        v0 = v.x; v1 = v.y;
    }
    split_pack(v0, v1, h, l);
}
template <int VEC>
__device__ __forceinline__ void ld_frag(const float* p0, const float* p1, int c, int Kreal,
                                        u32* fh, u32* fl) {
    if (VEC) {
        ld_split2(p0, c, Kreal, fh[0], fl[0]);
        ld_split2(p1, c, Kreal, fh[1], fl[1]);
        ld_split2(p0, c + 8, Kreal, fh[2], fl[2]);
        ld_split2(p1, c + 8, Kreal, fh[3], fl[3]);
    } else {
        ld_split(p0, c, Kreal, fh[0], fl[0]);
        ld_split(p1, c, Kreal, fh[1], fl[1]);
        ld_split(p0, c + 8, Kreal, fh[2], fl[2]);
        ld_split(p1, c + 8, Kreal, fh[3], fl[3]);
    }
}

// Streaming tower layer (N=72, NB=9): A frags loaded per-kb (double-buffered),
// 3 passes per kb (Ah*Wh, Al*Wh, Ah*Wl).
template <int KB, int VEC>
__device__ void tower_layer(const float* __restrict__ p0, const float* __restrict__ p1,
                            int Kreal, const char* smc, u32 offH, u32 offL, int bidx,
                            int lane, float* D) {
    const int t2 = (lane & 3) << 1;
    const float* biasp = reinterpret_cast<const float*>(smc + BIAS_B) + bidx;
    float acc[36];
#pragma unroll
    for (int nb = 0; nb < 9; nb++) {
        float2 bv = *reinterpret_cast<const float2*>(biasp + nb * 8 + t2);
        acc[4 * nb + 0] = bv.x; acc[4 * nb + 1] = bv.y;
        acc[4 * nb + 2] = bv.x; acc[4 * nb + 3] = bv.y;
    }
    const char* ph = smc + offH + (lane << 3);
    const char* pl = smc + offL + (lane << 3);
    u32 cfh[4], cfl[4], nfh[4], nfl[4];
    ld_frag<VEC>(p0, p1, t2, Kreal, cfh, cfl);
#pragma unroll
    for (int kb = 0; kb < KB; kb++) {
        if (kb + 1 < KB) ld_frag<VEC>(p0, p1, (kb + 1) * 16 + t2, Kreal, nfh, nfl);
        u32 b0[9], b1[9];
#pragma unroll
        for (int nb = 0; nb < 9; nb++) {
            ull w = *reinterpret_cast<const ull*>(ph + (kb * 9 + nb) * 256);
            b0[nb] = (u32)w; b1[nb] = (u32)(w >> 32);
            mma16816(acc[4 * nb + 0], acc[4 * nb + 1], acc[4 * nb + 2], acc[4 * nb + 3],
                     cfh[0], cfh[1], cfh[2], cfh[3], b0[nb], b1[nb]);
        }
#pragma unroll
        for (int nb = 0; nb < 9; nb++)
            mma16816(acc[4 * nb + 0], acc[4 * nb + 1], acc[4 * nb + 2], acc[4 * nb + 3],
                     cfl[0], cfl[1], cfl[2], cfl[3], b0[nb], b1[nb]);
#pragma unroll
        for (int nb = 0; nb < 9; nb++) {
            ull w = *reinterpret_cast<const ull*>(pl + (kb * 9 + nb) * 256);
            mma16816(acc[4 * nb + 0], acc[4 * nb + 1], acc[4 * nb + 2], acc[4 * nb + 3],
                     cfh[0], cfh[1], cfh[2], cfh[3], (u32)w, (u32)(w >> 32));
        }
#pragma unroll
        for (int i = 0; i < 4; i++) { cfh[i] = nfh[i]; cfl[i] = nfl[i]; }
    }
#pragma unroll
    for (int i = 0; i < 36; i++) D[i] = acc[i];
}

// One L0 k-block (16 concat cols = slots 2kb,2kb+1) against rolling frag buffer sh/sl[4].
__device__ __forceinline__ void l0_kb(float* acc, const u32* sh, const u32* sl, int kb,
                                      const char* smc, int lane) {
    const char* ph = smc + L0_H + (lane << 3);
    const char* pl = smc + L0_L + (lane << 3);
    u32 b0[5], b1[5];
#pragma unroll
    for (int nb = 0; nb < 5; nb++) {
        ull w = *reinterpret_cast<const ull*>(ph + (kb * 5 + nb) * 256);
        b0[nb] = (u32)w; b1[nb] = (u32)(w >> 32);
        mma16816(acc[4 * nb + 0], acc[4 * nb + 1], acc[4 * nb + 2], acc[4 * nb + 3],
                 sh[0], sh[1], sh[2], sh[3], b0[nb], b1[nb]);
    }
#pragma unroll
    for (int nb = 0; nb < 5; nb++)
        mma16816(acc[4 * nb + 0], acc[4 * nb + 1], acc[4 * nb + 2], acc[4 * nb + 3],
                 sl[0], sl[1], sl[2], sl[3], b0[nb], b1[nb]);
#pragma unroll
    for (int nb = 0; nb < 5; nb++) {
        ull w = *reinterpret_cast<const ull*>(pl + (kb * 5 + nb) * 256);
        mma16816(acc[4 * nb + 0], acc[4 * nb + 1], acc[4 * nb + 2], acc[4 * nb + 3],
                 sh[0], sh[1], sh[2], sh[3], (u32)w, (u32)(w >> 32));
    }
}

// Dense layer (kb outer / nb inner) for L1..L7 chaining on register fragments.
template <int KB, int NB>
__device__ __forceinline__ void layer(const u32* Ah, const u32* Al, const char* smc,
                                      u32 offH, u32 offL, int bidx, int lane, float* D) {
    const int t2 = (lane & 3) << 1;
    const float* biasp = reinterpret_cast<const float*>(smc + BIAS_B) + bidx;
    float acc[4 * NB];
#pragma unroll
    for (int nb = 0; nb < NB; nb++) {
        float2 bv = *reinterpret_cast<const float2*>(biasp + nb * 8 + t2);
        acc[4 * nb + 0] = bv.x; acc[4 * nb + 1] = bv.y;
        acc[4 * nb + 2] = bv.x; acc[4 * nb + 3] = bv.y;
    }
    const char* ph = smc + offH + (lane << 3);
    const char* pl = smc + offL + (lane << 3);
#pragma unroll
    for (int kb = 0; kb < KB; kb++) {
        u32 b0[NB], b1[NB];
#pragma unroll
        for (int nb = 0; nb < NB; nb++) {
            ull w = *reinterpret_cast<const ull*>(ph + (kb * NB + nb) * 256);
            b0[nb] = (u32)w; b1[nb] = (u32)(w >> 32);
            mma16816(acc[4 * nb + 0], acc[4 * nb + 1], acc[4 * nb + 2], acc[4 * nb + 3],
                     Ah[4 * kb], Ah[4 * kb + 1], Ah[4 * kb + 2], Ah[4 * kb + 3], b0[nb], b1[nb]);
        }
#pragma unroll
        for (int nb = 0; nb < NB; nb++)
            mma16816(acc[4 * nb + 0], acc[4 * nb + 1], acc[4 * nb + 2], acc[4 * nb + 3],
                     Al[4 * kb], Al[4 * kb + 1], Al[4 * kb + 2], Al[4 * kb + 3], b0[nb], b1[nb]);
    }
#pragma unroll
    for (int kb = 0; kb < KB; kb++) {
#pragma unroll
        for (int nb = 0; nb < NB; nb++) {
            ull w = *reinterpret_cast<const ull*>(pl + (kb * NB + nb) * 256);
            mma16816(acc[4 * nb + 0], acc[4 * nb + 1], acc[4 * nb + 2], acc[4 * nb + 3],
                     Ah[4 * kb], Ah[4 * kb + 1], Ah[4 * kb + 2], Ah[4 * kb + 3],
                     (u32)w, (u32)(w >> 32));
        }
    }
#pragma unroll
    for (int i = 0; i < 4 * NB; i++) D[i] = acc[i];
}

// W [K,N] row-major fp32 -> hi/lo B fragments. mode 1 = L0 concat row remap (Kp=144).
__device__ void prepW(char* smc, const float* __restrict__ W, int K, int N, int NBfr,
                      u32 offH, u32 offL, int tid, int nt, int mode) {
    for (int i = tid; i < K * N; i += nt) {
        int k = i / N, n = i - k * N;
        int kp = k;
        if (mode == 1) kp = (k < 68) ? k : k + 4;  // towerA 0-67, towerB 72-139, meta 140-143
        u32 fo = (u32)(((kp >> 4) * NBfr + (n >> 3)) << 8)
               + (u32)((((n & 7) << 2) | ((kp & 7) >> 1)) << 3)
               + (u32)(((kp >> 3) & 1) << 2)
               + (u32)((kp & 1) << 1);
        float v = W[i];
        __nv_bfloat16 h = __float2bfloat16(v);
        float lo = v - __bfloat162float(h);
        *reinterpret_cast<__nv_bfloat16*>(smc + offH + fo) = h;
        *reinterpret_cast<__nv_bfloat16*>(smc + offL + fo) = __float2bfloat16(lo);
    }
}

__global__ __launch_bounds__(576)
void Net_67954972557347_kernel(
    const float* __restrict__ a, const float* __restrict__ b, const float* __restrict__ meta,
    const float* __restrict__ Wa, const float* __restrict__ ba,
    const float* __restrict__ Wb, const float* __restrict__ bb,
    const float* __restrict__ W0, const float* __restrict__ B0,
    const float* __restrict__ W1, const float* __restrict__ B1,
    const float* __restrict__ W2, const float* __restrict__ B2,
    const float* __restrict__ W3, const float* __restrict__ B3,
    const float* __restrict__ W4, const float* __restrict__ B4,
    const float* __restrict__ W5, const float* __restrict__ B5,
    const float* __restrict__ W6, const float* __restrict__ B6,
    const float* __restrict__ W7, const float* __restrict__ B7,
    const float* __restrict__ W8, const float* __restrict__ B8,
    const float* __restrict__ W9, const float* __restrict__ B9,
    float* __restrict__ outp, int ntiles)
{
    extern __shared__ char smc[];
    const int tid = threadIdx.x, nt = blockDim.x, lane = tid & 31;

    for (u32 o = (u32)tid * 16; o < SMEM_TOTAL; o += (u32)nt * 16)
        *reinterpret_cast<uint4*>(smc + o) = make_uint4(0, 0, 0, 0);
    __syncthreads();

    prepW(smc, Wa, 45, 68, 9, TA_H, TA_L, tid, nt, 0);
    prepW(smc, Wb, 102, 68, 9, TB_H, TB_L, tid, nt, 0);
    prepW(smc, W0, 140, 34, 5, L0_H, L0_L, tid, nt, 1);
    prepW(smc, W1, 34, 34, 5, L1_H, L1_L, tid, nt, 0);
    prepW(smc, W2, 34, 20, 3, L2_H, L2_L, tid, nt, 0);
    prepW(smc, W3, 20, 20, 3, L3_H, L3_L, tid, nt, 0);
    prepW(smc, W4, 20, 20, 3, L4_H, L4_L, tid, nt, 0);
    prepW(smc, W5, 20, 20, 3, L5_H, L5_L, tid, nt, 0);
    prepW(smc, W6, 20, 20, 3, L6_H, L6_L, tid, nt, 0);
    prepW(smc, W7, 20, 5, 1, L7_H, L7_L, tid, nt, 0);
    float* bs = reinterpret_cast<float*>(smc + BIAS_B);
    if (tid < 68) { bs[JTA + tid] = ba[tid]; bs[JTB + tid] = bb[tid]; }
    if (tid < 34) { bs[J0 + tid] = B0[tid]; bs[J1 + tid] = B1[tid]; }
    if (tid < 20) {
        bs[J2 + tid] = B2[tid]; bs[J3 + tid] = B3[tid]; bs[J4 + tid] = B4[tid];
        bs[J5 + tid] = B5[tid]; bs[J6 + tid] = B6[tid];
    }
    if (tid < 5)  bs[J7 + tid] = B7[tid];
    if (tid < 10) bs[JW8 + tid] = W8[tid];
    if (tid < 2)  { bs[JB8 + tid] = B8[tid]; bs[JW9 + tid] = W9[tid]; }
    if (tid == 0) bs[JB9] = B9[0];
    __syncthreads();

    const int t2 = (lane & 3) << 1;

    for (;;) {
        int tile;
        if (lane == 0) tile = atomicAdd(&g_ctr, 1);
        tile = __shfl_sync(0xFFFFFFFFu, tile, 0);
        if (tile >= ntiles) break;

        const int r0 = tile * 16 + (lane >> 2), r1 = r0 + 8;

        // L0 accumulator (fused) + rolling 2-slot fragment buffer
        float accL0[20];
#pragma unroll
        for (int nb = 0; nb < 5; nb++) {
            float2 bv = *reinterpret_cast<const float2*>(bs + J0 + nb * 8 + t2);
            accL0[4 * nb + 0] = bv.x; accL0[4 * nb + 1] = bv.y;
            accL0[4 * nb + 2] = bv.x; accL0[4 * nb + 3] = bv.y;
        }
        u32 sh[4], sl[4];

        {   // tower A (concat slots 0..8; fires L0 kb 0..3, slot 8 pending)
            float D[36];
            tower_layer<3, 0>(a + (size_t)r0 * 45, a + (size_t)r1 * 45, 45,
                              smc, TA_H, TA_L, JTA, lane, D);
#pragma unroll
            for (int nb = 0; nb < 9; nb++) {
                int half = nb & 1;
                float d0 = lrelu(D[4 * nb + 0]), d1 = lrelu(D[4 * nb + 1]);
                float d2 = lrelu(D[4 * nb + 2]), d3 = lrelu(D[4 * nb + 3]);
                split_pack(d0, d1, sh[2 * half + 0], sl[2 * half + 0]);
                split_pack(d2, d3, sh[2 * half + 1], sl[2 * half + 1]);
                if (half) l0_kb(accL0, sh, sl, nb >> 1, smc, lane);
            }
        }
        {   // tower B (concat slots 9..17; meta merged into slot 17 cols 4..7)
            float D[36];
            tower_layer<7, 1>(b + (size_t)r0 * 102, b + (size_t)r1 * 102, 102,
                              smc, TB_H, TB_L, JTB, lane, D);
#pragma unroll
            for (int nb = 0; nb < 8; nb++) {
                int half = (nb + 1) & 1;   // slot 9+nb
                float d0 = lrelu(D[4 * nb + 0]), d1 = lrelu(D[4 * nb + 1]);
                float d2 = lrelu(D[4 * nb + 2]), d3 = lrelu(D[4 * nb + 3]);
                split_pack(d0, d1, sh[2 * half + 0], sl[2 * half + 0]);
                split_pack(d2, d3, sh[2 * half + 1], sl[2 * half + 1]);
                if (half) l0_kb(accL0, sh, sl, (9 + nb) >> 1, smc, lane);
            }
            {   // nb=8 -> slot 17 (odd): cols 0-3 = towerB outs 64-67, cols 4-7 = meta (no lrelu)
                float e0, e1, e2, e3;
                if (t2 < 4) {
                    e0 = lrelu(D[32]); e1 = lrelu(D[33]);
                    e2 = lrelu(D[34]); e3 = lrelu(D[35]);
                } else {
                    float2 u = *reinterpret_cast<const float2*>(meta + (size_t)r0 * 4 + (t2 - 4));
                    float2 v = *reinterpret_cast<const float2*>(meta + (size_t)r1 * 4 + (t2 - 4));
                    e0 = u.x; e1 = u.y; e2 = v.x; e3 = v.y;
                }
                split_pack(e0, e1, sh[2], sl[2]);
                split_pack(e2, e3, sh[3], sl[3]);
                l0_kb(accL0, sh, sl, 8, smc, lane);
            }
        }

        // L0 outputs -> fragments for L1
        u32 h1[12], l1[12];
#pragma unroll
        for (int nb = 0; nb < 5; nb++)
            toslot(accL0[4 * nb], accL0[4 * nb + 1], accL0[4 * nb + 2], accL0[4 * nb + 3],
                   h1, l1, nb, true);
        h1[10] = 0; h1[11] = 0; l1[10] = 0; l1[11] = 0;

        {   // L1: K=48, N=40
            float D[20];
            layer<3, 5>(h1, l1, smc, L1_H, L1_L, J1, lane, D);
#pragma unroll
            for (int nb = 0; nb < 5; nb++)
                toslot(D[4 * nb], D[4 * nb + 1], D[4 * nb + 2], D[4 * nb + 3], h1, l1, nb, true);
            h1[10] = 0; h1[11] = 0; l1[10] = 0; l1[11] = 0;
        }
        {   // L2: K=48, N=24
            float D[12];
            layer<3, 3>(h1, l1, smc, L2_H, L2_L, J2, lane, D);
#pragma unroll
            for (int nb = 0; nb < 3; nb++)
                toslot(D[4 * nb], D[4 * nb + 1], D[4 * nb + 2], D[4 * nb + 3], h1, l1, nb, true);
            h1[6] = 0; h1[7] = 0; l1[6] = 0; l1[7] = 0;
        }
        const u32 lh[4] = { L3_H, L4_H, L5_H, L6_H };
        const u32 ll[4] = { L3_L, L4_L, L5_L, L6_L };
        const int lj[4] = { J3, J4, J5, J6 };
#pragma unroll
        for (int L = 0; L < 4; L++) {
            float D[12];
            layer<2, 3>(h1, l1, smc, lh[L], ll[L], lj[L], lane, D);
#pragma unroll
            for (int nb = 0; nb < 3; nb++)
                toslot(D[4 * nb], D[4 * nb + 1], D[4 * nb + 2], D[4 * nb + 3], h1, l1, nb, true);
            h1[6] = 0; h1[7] = 0; l1[6] = 0; l1[7] = 0;
        }
        // L7: K=32, N=8
        float D7[4];
        layer<2, 1>(h1, l1, smc, L7_H, L7_L, J7, lane, D7);
        float v0 = lrelu(D7[0]), v1 = lrelu(D7[1]), v2 = lrelu(D7[2]), v3 = lrelu(D7[3]);

        // L8 (5->2) + L9 (2->1) scalar; 4-lane butterfly per row group
        float w8a0 = bs[JW8 + t2 * 2 + 0], w8b0 = bs[JW8 + t2 * 2 + 1];
        float w8a1 = bs[JW8 + (t2 + 1) * 2 + 0], w8b1 = bs[JW8 + (t2 + 1) * 2 + 1];
        float pa0 = fmaf(v0, w8a0, v1 * w8a1), pb0 = fmaf(v0, w8b0, v1 * w8b1);
        float pa1 = fmaf(v2, w8a0, v3 * w8a1), pb1 = fmaf(v2, w8b0, v3 * w8b1);
        pa0 += __shfl_xor_sync(0xFFFFFFFFu, pa0, 1); pa0 += __shfl_xor_sync(0xFFFFFFFFu, pa0, 2);
        pb0 += __shfl_xor_sync(0xFFFFFFFFu, pb0, 1); pb0 += __shfl_xor_sync(0xFFFFFFFFu, pb0, 2);
        pa1 += __shfl_xor_sync(0xFFFFFFFFu, pa1, 1); pa1 += __shfl_xor_sync(0xFFFFFFFFu, pa1, 2);
        pb1 += __shfl_xor_sync(0xFFFFFFFFu, pb1, 1); pb1 += __shfl_xor_sync(0xFFFFFFFFu, pb1, 2);
        float w90 = bs[JW9 + 0], w91 = bs[JW9 + 1], b9v = bs[JB9];
        float c8a = lrelu(pa0 + bs[JB8 + 0]), c8b = lrelu(pb0 + bs[JB8 + 1]);
        float o0 = lrelu(fmaf(c8a, w90, fmaf(c8b, w91, b9v)));
        c8a = lrelu(pa1 + bs[JB8 + 0]); c8b = lrelu(pb1 + bs[JB8 + 1]);
        float o1 = lrelu(fmaf(c8a, w90, fmaf(c8b, w91, b9v)));
        if ((lane & 3) == 0) { outp[r0] = o0; outp[r1] = o1; }
    }
}

extern "C" void kernel_launch(void* const* d_in, const int* in_sizes, int n_in,
                              void* d_out, int out_size) {
    const float* a    = (const float*)d_in[0];
    const float* b    = (const float*)d_in[1];
    const float* meta = (const float*)d_in[2];
    const float* Wa   = (const float*)d_in[3];
    const float* ba   = (const float*)d_in[4];
    const float* Wb   = (const float*)d_in[5];
    const float* bb   = (const float*)d_in[6];
    const float* W[10], *Bb[10];
    for (int i = 0; i < 10; i++) {
        W[i]  = (const float*)d_in[7 + 2 * i];
        Bb[i] = (const float*)d_in[8 + 2 * i];
    }
    float* outp = (float*)d_out;
    const int nrows = in_sizes[0] / 45;
    const int ntiles = nrows / 16;   // 16384

    cudaFuncSetAttribute(Net_67954972557347_kernel,
                         cudaFuncAttributeMaxDynamicSharedMemorySize, SMEM_TOTAL);

    reset_ctr_kernel<<<1, 1>>>();
    // 96.5 KB smem, 1 CTA/SM x 576 threads = 18 warps (reg cap 112 >= measured 102).
    Net_67954972557347_kernel<<<148, 576, SMEM_TOTAL>>>(
        a, b, meta, Wa, ba, Wb, bb,
        W[0], Bb[0], W[1], Bb[1], W[2], Bb[2], W[3], Bb[3], W[4], Bb[4],
        W[5], Bb[5], W[6], Bb[6], W[7], Bb[7], W[8], Bb[8], W[9], Bb[9],
        outp, ntiles);
}